// round 7
// baseline (speedup 1.0000x reference)
#include <cuda_runtime.h>
#include <math.h>

#define D_MODEL 1024
#define D_STATE 64
#define D_CONV  4
#define D_INNER 2048
#define NHEADS  32
#define HEADDIM 64
#define D_PROJ  8224   // 2*D_INNER + NHEADS*(2*D_STATE+1)
#define BATCH   2
#define SEQLEN  1024
#define NTOK    (BATCH*SEQLEN)   // 2048
#define CHUNK   64
#define NCHUNK  (SEQLEN/CHUNK)   // 16

// Scratch (allocation-free rule: __device__ globals)
__device__ float g_proj [(size_t)NTOK * D_PROJ];          // 67 MB
__device__ float g_xconv[(size_t)NTOK * D_INNER];         // 17 MB
__device__ float g_y    [(size_t)NTOK * D_INNER];         // 17 MB
__device__ float g_S    [(size_t)BATCH*NHEADS*SEQLEN];    // 256 KB (per-chunk dt cumsum)
__device__ float g_hloc [(size_t)BATCH*NHEADS*NCHUNK*D_STATE*HEADDIM]; // 17 MB
__device__ float g_hin  [(size_t)BATCH*NHEADS*NCHUNK*D_STATE*HEADDIM]; // 17 MB

// ---------------------------------------------------------------------------
// SGEMM "NT": C[m,n] = sum_k A[m*K+k] * B[n*K+k]
// Block tile 128x128, K-tile 8, 256 threads, 8x8 per-thread microtile.
// ---------------------------------------------------------------------------
__global__ __launch_bounds__(256) void sgemm_nt(
    const float* __restrict__ A, const float* __restrict__ B,
    float* __restrict__ C, int M, int N, int K)
{
    const int tid = threadIdx.x;
    const int bm  = blockIdx.y * 128;
    const int bn  = blockIdx.x * 128;

    __shared__ float As[8][128];
    __shared__ float Bs[8][128];

    const int lrow = tid >> 1;        // 0..127
    const int lk   = (tid & 1) * 4;   // 0 or 4

    const int tx = tid & 15;          // 0..15 -> n microtile
    const int ty = tid >> 4;          // 0..15 -> m microtile

    float acc[8][8];
    #pragma unroll
    for (int i = 0; i < 8; i++)
        #pragma unroll
        for (int j = 0; j < 8; j++)
            acc[i][j] = 0.f;

    const float* Aptr = A + (size_t)(bm + lrow) * K + lk;
    const bool bvalid = (bn + lrow) < N;
    const float* Bptr = B + (size_t)(bvalid ? (bn + lrow) : 0) * K + lk;

    for (int kt = 0; kt < K; kt += 8) {
        float4 av = *reinterpret_cast<const float4*>(Aptr + kt);
        float4 bv = bvalid ? *reinterpret_cast<const float4*>(Bptr + kt)
                           : make_float4(0.f, 0.f, 0.f, 0.f);
        As[lk + 0][lrow] = av.x; As[lk + 1][lrow] = av.y;
        As[lk + 2][lrow] = av.z; As[lk + 3][lrow] = av.w;
        Bs[lk + 0][lrow] = bv.x; Bs[lk + 1][lrow] = bv.y;
        Bs[lk + 2][lrow] = bv.z; Bs[lk + 3][lrow] = bv.w;
        __syncthreads();

        #pragma unroll
        for (int k = 0; k < 8; k++) {
            float4 a0 = *reinterpret_cast<const float4*>(&As[k][ty * 8]);
            float4 a1 = *reinterpret_cast<const float4*>(&As[k][ty * 8 + 4]);
            float4 b0 = *reinterpret_cast<const float4*>(&Bs[k][tx * 8]);
            float4 b1 = *reinterpret_cast<const float4*>(&Bs[k][tx * 8 + 4]);
            float a[8] = {a0.x, a0.y, a0.z, a0.w, a1.x, a1.y, a1.z, a1.w};
            float b[8] = {b0.x, b0.y, b0.z, b0.w, b1.x, b1.y, b1.z, b1.w};
            #pragma unroll
            for (int i = 0; i < 8; i++)
                #pragma unroll
                for (int j = 0; j < 8; j++)
                    acc[i][j] = fmaf(a[i], b[j], acc[i][j]);
        }
        __syncthreads();
    }

    #pragma unroll
    for (int i = 0; i < 8; i++) {
        const int m = bm + ty * 8 + i;
        #pragma unroll
        for (int j = 0; j < 8; j++) {
            const int n = bn + tx * 8 + j;
            if (n < N) C[(size_t)m * N + n] = acc[i][j];
        }
    }
}

// ---------------------------------------------------------------------------
// Depthwise causal conv (width 4) + bias + SiLU
// ---------------------------------------------------------------------------
__global__ __launch_bounds__(256) void conv_silu_kernel(
    const float* __restrict__ conv_w, const float* __restrict__ conv_b)
{
    const int idx = blockIdx.x * blockDim.x + threadIdx.x;
    if (idx >= NTOK * D_INNER) return;
    const int c   = idx & (D_INNER - 1);
    const int tok = idx / D_INNER;
    const int b   = tok / SEQLEN;
    const int l   = tok - b * SEQLEN;

    float acc = conv_b[c];
    #pragma unroll
    for (int j = 0; j < D_CONV; j++) {
        const int ll = l - (D_CONV - 1) + j;
        if (ll >= 0)
            acc = fmaf(conv_w[c * D_CONV + j],
                       g_proj[(size_t)(b * SEQLEN + ll) * D_PROJ + c], acc);
    }
    const float sv = acc / (1.f + expf(-acc));   // SiLU
    g_xconv[(size_t)tok * D_INNER + c] = sv;
}

// ---------------------------------------------------------------------------
// Phase A: chunk-local scan with h_in = 0. One CTA per (head, batch, chunk).
// 128 threads: thread (d = tid>>1, sq = tid&1) owns states [32*sq, 32*sq+32)
// of head-dim column d. Emits:
//   g_y    : raw chunk-local y (no D*x, no gating)
//   g_S    : within-chunk inclusive cumsum of dt  (per token)
//   g_hloc : chunk-local final state local_T[s][d]
// ---------------------------------------------------------------------------
__global__ __launch_bounds__(128) void scan_chunk_kernel(
    const float* __restrict__ A_log, const float* __restrict__ dt_bias)
{
    const int h   = blockIdx.x;
    const int b   = blockIdx.y;
    const int c   = blockIdx.z;
    const int tid = threadIdx.x;
    const int d   = tid >> 1;
    const int sq  = tid & 1;
    const int s0  = sq * 32;

    __shared__ float4 sABC[D_STATE];  // {dA, dB*dt, C, pad}

    float Aneg = 0.f;
    if (tid < D_STATE) Aneg = -expf(A_log[h * D_STATE + tid]);
    const float dtb = dt_bias[h];

    float hreg[32];
    #pragma unroll
    for (int i = 0; i < 32; i++) hreg[i] = 0.f;

    const int bc_off = 2 * D_INNER + h * (2 * D_STATE + 1);
    const int x_off  = h * HEADDIM + d;

    int tok = b * SEQLEN + c * CHUNK;
    const float* prow0 = g_proj + (size_t)tok * D_PROJ;
    float pBC = prow0[bc_off + tid];
    float pdt = prow0[bc_off + 2 * D_STATE];
    float px  = g_xconv[(size_t)tok * D_INNER + x_off];

    float S = 0.f;
    float* Sout = g_S + (size_t)(b * NHEADS + h) * SEQLEN + c * CHUNK;

    for (int l = 0; l < CHUNK; l++) {
        const float dtraw = pdt + dtb;
        const float dt = (dtraw > 20.f) ? dtraw : log1pf(expf(dtraw));
        S += dt;
        if (tid < D_STATE) {
            sABC[tid].x = expf(Aneg * dt);
            sABC[tid].y = pBC * dt;
        } else {
            sABC[tid - D_STATE].z = pBC;
        }
        const float xd = px;

        // prefetch next step (clamped inside chunk)
        {
            const int ln   = (l + 1 < CHUNK) ? (l + 1) : l;
            const int tokn = b * SEQLEN + c * CHUNK + ln;
            const float* prown = g_proj + (size_t)tokn * D_PROJ;
            pBC = prown[bc_off + tid];
            pdt = prown[bc_off + 2 * D_STATE];
            px  = g_xconv[(size_t)tokn * D_INNER + x_off];
        }

        __syncthreads();

        float y0 = 0.f, y1 = 0.f, y2 = 0.f, y3 = 0.f;
        #pragma unroll
        for (int i = 0; i < 32; i += 4) {
            float4 v0 = sABC[s0 + i + 0];
            float4 v1 = sABC[s0 + i + 1];
            float4 v2 = sABC[s0 + i + 2];
            float4 v3 = sABC[s0 + i + 3];
            hreg[i + 0] = fmaf(v0.x, hreg[i + 0], v0.y * xd);
            hreg[i + 1] = fmaf(v1.x, hreg[i + 1], v1.y * xd);
            hreg[i + 2] = fmaf(v2.x, hreg[i + 2], v2.y * xd);
            hreg[i + 3] = fmaf(v3.x, hreg[i + 3], v3.y * xd);
            y0 = fmaf(v0.z, hreg[i + 0], y0);
            y1 = fmaf(v1.z, hreg[i + 1], y1);
            y2 = fmaf(v2.z, hreg[i + 2], y2);
            y3 = fmaf(v3.z, hreg[i + 3], y3);
        }
        float y = (y0 + y1) + (y2 + y3);
        y += __shfl_xor_sync(0xffffffffu, y, 1);   // partner lane shares d

        if (sq == 0)
            g_y[(size_t)tok * D_INNER + x_off] = y;   // raw local y
        if (tid == 0)
            Sout[l] = S;

        tok++;
        __syncthreads();
    }

    // write chunk-local final state
    float* hl = g_hloc + ((size_t)(b * NHEADS + h) * NCHUNK + c) * (D_STATE * HEADDIM);
    #pragma unroll
    for (int i = 0; i < 32; i++)
        hl[(s0 + i) * HEADDIM + d] = hreg[i];
}

// ---------------------------------------------------------------------------
// Phase B: cross-chunk state recurrence. One thread per (b,h,s,d); 16
// sequential chunk steps, fully parallel otherwise.
//   g_hin[c] = incoming state of chunk c  (c=0 -> zeros)
// ---------------------------------------------------------------------------
__global__ __launch_bounds__(256) void chunk_state_kernel(
    const float* __restrict__ A_log)
{
    const int gid = blockIdx.x * 256 + threadIdx.x;  // 2^18 threads
    const int dd = gid & 63;
    const int s  = (gid >> 6) & 63;
    const int hh = (gid >> 12) & 31;
    const int bb = gid >> 17;

    const float Aneg = -expf(A_log[hh * D_STATE + s]);
    const size_t base = ((size_t)(bb * NHEADS + hh) * NCHUNK) * (D_STATE * HEADDIM)
                      + (size_t)s * HEADDIM + dd;
    const float* Srow = g_S + (size_t)(bb * NHEADS + hh) * SEQLEN;

    float hv = 0.f;
    #pragma unroll
    for (int cc = 0; cc < NCHUNK; cc++) {
        g_hin[base + (size_t)cc * (D_STATE * HEADDIM)] = hv;
        const float ST = Srow[cc * CHUNK + CHUNK - 1];
        hv = fmaf(expf(Aneg * ST), hv,
                  g_hloc[base + (size_t)cc * (D_STATE * HEADDIM)]);
    }
}

// ---------------------------------------------------------------------------
// Phase C: per chunk, y_t += sum_s C_t[s]*exp(Aneg_s*S_t)*h_in[s,d],
// then finalize: g_y = (y + D*x) * silu(z).
// One CTA per (head, batch, chunk), 256 threads.
// Thread (t = tid&63, d0 = (tid>>6)*16) computes 16 outputs.
// ---------------------------------------------------------------------------
__global__ __launch_bounds__(256) void ycorrect_kernel(
    const float* __restrict__ A_log, const float* __restrict__ Dp)
{
    const int h   = blockIdx.x;
    const int b   = blockIdx.y;
    const int c   = blockIdx.z;
    const int tid = threadIdx.x;

    __shared__ float sHin[D_STATE * HEADDIM];   // [s][d]
    __shared__ float sCt[CHUNK * 65];           // [t][s], padded
    __shared__ float sS[CHUNK];
    __shared__ float sAneg[D_STATE];

    const size_t hin_base = ((size_t)(b * NHEADS + h) * NCHUNK + c) * (D_STATE * HEADDIM);
    for (int i = tid; i < D_STATE * HEADDIM; i += 256)
        sHin[i] = g_hin[hin_base + i];

    if (tid < D_STATE) {
        sAneg[tid] = -expf(A_log[h * D_STATE + tid]);
        sS[tid] = g_S[(size_t)(b * NHEADS + h) * SEQLEN + c * CHUNK + tid];
    }
    __syncthreads();

    const int bc_off = 2 * D_INNER + h * (2 * D_STATE + 1);
    const int tok0   = b * SEQLEN + c * CHUNK;

    // fill Ctilde[t][s] = C_t[s] * exp(Aneg_s * S_t)   (16 entries/thread)
    #pragma unroll
    for (int j = 0; j < 16; j++) {
        const int idx = tid * 16 + j;
        const int t = idx >> 6, s = idx & 63;
        const float Cv = g_proj[(size_t)(tok0 + t) * D_PROJ + bc_off + D_STATE + s];
        sCt[t * 65 + s] = Cv * expf(sAneg[s] * sS[t]);
    }
    __syncthreads();

    const int t  = tid & 63;
    const int d0 = (tid >> 6) * 16;

    float acc[16];
    #pragma unroll
    for (int i = 0; i < 16; i++) acc[i] = 0.f;

    #pragma unroll 8
    for (int s = 0; s < D_STATE; s++) {
        const float ct = sCt[t * 65 + s];
        const float* hr = &sHin[s * HEADDIM + d0];
        #pragma unroll
        for (int i = 0; i < 16; i += 4) {
            const float4 hv = *reinterpret_cast<const float4*>(hr + i);
            acc[i + 0] = fmaf(ct, hv.x, acc[i + 0]);
            acc[i + 1] = fmaf(ct, hv.y, acc[i + 1]);
            acc[i + 2] = fmaf(ct, hv.z, acc[i + 2]);
            acc[i + 3] = fmaf(ct, hv.w, acc[i + 3]);
        }
    }

    // finalize: y = (y_local + corr + D*x) * silu(z)
    const float Dh  = Dp[h];
    const int tok   = tok0 + t;
    const float* prow = g_proj  + (size_t)tok * D_PROJ;
    const float* xrow = g_xconv + (size_t)tok * D_INNER + h * HEADDIM;
    float*       yrow = g_y     + (size_t)tok * D_INNER + h * HEADDIM;
    #pragma unroll
    for (int i = 0; i < 16; i++) {
        const int dd = d0 + i;
        const float xv = xrow[dd];
        const float zv = prow[D_INNER + h * HEADDIM + dd];
        const float y  = yrow[dd] + acc[i] + Dh * xv;
        const float sz = zv / (1.f + expf(-zv));
        yrow[dd] = y * sz;
    }
}

// ---------------------------------------------------------------------------
extern "C" void kernel_launch(void* const* d_in, const int* in_sizes, int n_in,
                              void* d_out, int out_size)
{
    const float* x       = (const float*)d_in[0];  // (2,1024,1024)
    const float* W_in    = (const float*)d_in[1];  // (8224,1024)
    const float* conv_w  = (const float*)d_in[2];  // (2048,1,4)
    const float* conv_b  = (const float*)d_in[3];  // (2048,)
    const float* A_log   = (const float*)d_in[4];  // (32,64)
    const float* Dp      = (const float*)d_in[5];  // (32,)
    const float* dt_bias = (const float*)d_in[6];  // (32,)
    const float* W_out   = (const float*)d_in[7];  // (1024,2048)
    float* out = (float*)d_out;                    // (2,1024,1024)

    (void)in_sizes; (void)n_in; (void)out_size;

    float* proj = nullptr;
    cudaGetSymbolAddress((void**)&proj, g_proj);

    // 1) proj = x @ W_in^T   (M=2048, N=8224, K=1024)
    {
        dim3 grid((D_PROJ + 127) / 128, NTOK / 128);
        sgemm_nt<<<grid, 256>>>(x, W_in, proj, NTOK, D_PROJ, D_MODEL);
    }

    // 2) depthwise conv + SiLU
    {
        const int total = NTOK * D_INNER;
        conv_silu_kernel<<<(total + 255) / 256, 256>>>(conv_w, conv_b);
    }

    // 3a) chunk-local scans (parallel over 1024 chunks)
    {
        dim3 grid(NHEADS, BATCH, NCHUNK);
        scan_chunk_kernel<<<grid, 128>>>(A_log, dt_bias);
    }

    // 3b) cross-chunk state recurrence
    {
        const int total = BATCH * NHEADS * D_STATE * HEADDIM;   // 262144
        chunk_state_kernel<<<total / 256, 256>>>(A_log);
    }

    // 3c) y correction + D*x + gating
    {
        dim3 grid(NHEADS, BATCH, NCHUNK);
        ycorrect_kernel<<<grid, 256>>>(A_log, Dp);
    }

    // 4) out = y @ W_out^T   (M=2048, N=1024, K=2048)
    {
        float* yptr = nullptr;
        cudaGetSymbolAddress((void**)&yptr, g_y);
        dim3 grid(D_MODEL / 128, NTOK / 128);
        sgemm_nt<<<grid, 256>>>(yptr, W_out, out, NTOK, D_MODEL, D_INNER);
    }
}

// round 8
// speedup vs baseline: 1.4036x; 1.4036x over previous
#include <cuda_runtime.h>
#include <math.h>

#define D_MODEL 1024
#define D_STATE 64
#define D_CONV  4
#define D_INNER 2048
#define NHEADS  32
#define HEADDIM 64
#define D_PROJ  8224   // 2*D_INNER + NHEADS*(2*D_STATE+1)
#define BATCH   2
#define SEQLEN  1024
#define NTOK    (BATCH*SEQLEN)   // 2048
#define CHUNK   64
#define NCHUNK  (SEQLEN/CHUNK)   // 16

// Scratch (allocation-free rule: __device__ globals)
__device__ float g_proj [(size_t)NTOK * D_PROJ];          // 67 MB
__device__ float g_xconv[(size_t)NTOK * D_INNER];         // 17 MB
__device__ float g_y    [(size_t)NTOK * D_INNER];         // 17 MB
__device__ float g_S    [(size_t)BATCH*NHEADS*SEQLEN];    // 256 KB
__device__ float g_hloc [(size_t)BATCH*NHEADS*NCHUNK*D_STATE*HEADDIM]; // 17 MB
__device__ float g_hin  [(size_t)BATCH*NHEADS*NCHUNK*D_STATE*HEADDIM]; // 17 MB

// ---------------------------------------------------------------------------
// SGEMM "NT": C[m,n] = sum_k A[m*K+k] * B[n*K+k]
// ---------------------------------------------------------------------------
__global__ __launch_bounds__(256) void sgemm_nt(
    const float* __restrict__ A, const float* __restrict__ B,
    float* __restrict__ C, int M, int N, int K)
{
    const int tid = threadIdx.x;
    const int bm  = blockIdx.y * 128;
    const int bn  = blockIdx.x * 128;

    __shared__ float As[8][128];
    __shared__ float Bs[8][128];

    const int lrow = tid >> 1;
    const int lk   = (tid & 1) * 4;

    const int tx = tid & 15;
    const int ty = tid >> 4;

    float acc[8][8];
    #pragma unroll
    for (int i = 0; i < 8; i++)
        #pragma unroll
        for (int j = 0; j < 8; j++)
            acc[i][j] = 0.f;

    const float* Aptr = A + (size_t)(bm + lrow) * K + lk;
    const bool bvalid = (bn + lrow) < N;
    const float* Bptr = B + (size_t)(bvalid ? (bn + lrow) : 0) * K + lk;

    for (int kt = 0; kt < K; kt += 8) {
        float4 av = *reinterpret_cast<const float4*>(Aptr + kt);
        float4 bv = bvalid ? *reinterpret_cast<const float4*>(Bptr + kt)
                           : make_float4(0.f, 0.f, 0.f, 0.f);
        As[lk + 0][lrow] = av.x; As[lk + 1][lrow] = av.y;
        As[lk + 2][lrow] = av.z; As[lk + 3][lrow] = av.w;
        Bs[lk + 0][lrow] = bv.x; Bs[lk + 1][lrow] = bv.y;
        Bs[lk + 2][lrow] = bv.z; Bs[lk + 3][lrow] = bv.w;
        __syncthreads();

        #pragma unroll
        for (int k = 0; k < 8; k++) {
            float4 a0 = *reinterpret_cast<const float4*>(&As[k][ty * 8]);
            float4 a1 = *reinterpret_cast<const float4*>(&As[k][ty * 8 + 4]);
            float4 b0 = *reinterpret_cast<const float4*>(&Bs[k][tx * 8]);
            float4 b1 = *reinterpret_cast<const float4*>(&Bs[k][tx * 8 + 4]);
            float a[8] = {a0.x, a0.y, a0.z, a0.w, a1.x, a1.y, a1.z, a1.w};
            float b[8] = {b0.x, b0.y, b0.z, b0.w, b1.x, b1.y, b1.z, b1.w};
            #pragma unroll
            for (int i = 0; i < 8; i++)
                #pragma unroll
                for (int j = 0; j < 8; j++)
                    acc[i][j] = fmaf(a[i], b[j], acc[i][j]);
        }
        __syncthreads();
    }

    #pragma unroll
    for (int i = 0; i < 8; i++) {
        const int m = bm + ty * 8 + i;
        #pragma unroll
        for (int j = 0; j < 8; j++) {
            const int n = bn + tx * 8 + j;
            if (n < N) C[(size_t)m * N + n] = acc[i][j];
        }
    }
}

// ---------------------------------------------------------------------------
// Depthwise causal conv (width 4) + bias + SiLU
// ---------------------------------------------------------------------------
__global__ __launch_bounds__(256) void conv_silu_kernel(
    const float* __restrict__ conv_w, const float* __restrict__ conv_b)
{
    const int idx = blockIdx.x * blockDim.x + threadIdx.x;
    if (idx >= NTOK * D_INNER) return;
    const int c   = idx & (D_INNER - 1);
    const int tok = idx / D_INNER;
    const int b   = tok / SEQLEN;
    const int l   = tok - b * SEQLEN;

    float acc = conv_b[c];
    #pragma unroll
    for (int j = 0; j < D_CONV; j++) {
        const int ll = l - (D_CONV - 1) + j;
        if (ll >= 0)
            acc = fmaf(conv_w[c * D_CONV + j],
                       g_proj[(size_t)(b * SEQLEN + ll) * D_PROJ + c], acc);
    }
    const float sv = acc / (1.f + expf(-acc));   // SiLU
    g_xconv[(size_t)tok * D_INNER + c] = sv;
}

// ---------------------------------------------------------------------------
// Phase A (v3): warp-autonomous chunk-local scan, h_in = 0.
// Grid (NHEADS, BATCH, NCHUNK), 64 threads = 2 INDEPENDENT warps.
// Lane owns head-dim column d = tid and keeps all 64 states in registers;
// no cross-lane reduction needed. Each warp stages {dA, B*dt, C} per state
// in its OWN smem buffer: zero __syncthreads, only __syncwarp.
// Emits: g_y (raw local y), g_S (in-chunk dt cumsum), g_hloc (final state).
// ---------------------------------------------------------------------------
__global__ __launch_bounds__(64) void scan_chunk_kernel(
    const float* __restrict__ A_log, const float* __restrict__ dt_bias)
{
    const int h    = blockIdx.x;
    const int b    = blockIdx.y;
    const int c    = blockIdx.z;
    const int tid  = threadIdx.x;   // 0..63  == head-dim column d
    const int w    = tid >> 5;      // warp 0/1
    const int lane = tid & 31;

    __shared__ float4 sW[2][D_STATE];   // per-warp staging {dA, B*dt, C, 0}

    // This lane stages states s0 = 2*lane, s0+1 (within its warp's buffer)
    const int s0 = lane * 2;
    const float Aneg0 = -__expf(A_log[h * D_STATE + s0 + 0]);
    const float Aneg1 = -__expf(A_log[h * D_STATE + s0 + 1]);
    const float dtb   = dt_bias[h];

    float hreg[D_STATE];
    #pragma unroll
    for (int s = 0; s < D_STATE; s++) hreg[s] = 0.f;

    const int bc_off = 2 * D_INNER + h * (2 * D_STATE + 1);
    const int x_off  = h * HEADDIM + tid;

    int tok = b * SEQLEN + c * CHUNK;

    // ---- prefetch step 0 ----
    const float* prow0 = g_proj + (size_t)tok * D_PROJ;
    float pB0 = prow0[bc_off + s0 + 0];
    float pB1 = prow0[bc_off + s0 + 1];
    float pC0 = prow0[bc_off + D_STATE + s0 + 0];
    float pC1 = prow0[bc_off + D_STATE + s0 + 1];
    float pdt = prow0[bc_off + 2 * D_STATE];
    float px  = g_xconv[(size_t)tok * D_INNER + x_off];

    float S = 0.f;
    float* Sout = g_S + (size_t)(b * NHEADS + h) * SEQLEN + c * CHUNK;

    for (int l = 0; l < CHUNK; l++) {
        // ---- stage from prefetched registers (warp-private buffer) ----
        const float dtraw = pdt + dtb;
        const float dt = (dtraw > 20.f) ? dtraw : log1pf(__expf(dtraw));
        S += dt;
        sW[w][s0 + 0] = make_float4(__expf(Aneg0 * dt), pB0 * dt, pC0, 0.f);
        sW[w][s0 + 1] = make_float4(__expf(Aneg1 * dt), pB1 * dt, pC1, 0.f);
        const float xd = px;
        __syncwarp();

        // ---- prefetch next step (clamped inside chunk) ----
        {
            const int ln   = (l + 1 < CHUNK) ? (l + 1) : l;
            const int tokn = b * SEQLEN + c * CHUNK + ln;
            const float* prown = g_proj + (size_t)tokn * D_PROJ;
            pB0 = prown[bc_off + s0 + 0];
            pB1 = prown[bc_off + s0 + 1];
            pC0 = prown[bc_off + D_STATE + s0 + 0];
            pC1 = prown[bc_off + D_STATE + s0 + 1];
            pdt = prown[bc_off + 2 * D_STATE];
            px  = g_xconv[(size_t)tokn * D_INNER + x_off];
        }

        // ---- 64 state updates + y (4 independent accumulators) ----
        float y0 = 0.f, y1 = 0.f, y2 = 0.f, y3 = 0.f;
        #pragma unroll
        for (int s = 0; s < D_STATE; s += 4) {
            const float4 v0 = sW[w][s + 0];
            const float4 v1 = sW[w][s + 1];
            const float4 v2 = sW[w][s + 2];
            const float4 v3 = sW[w][s + 3];
            hreg[s + 0] = fmaf(v0.x, hreg[s + 0], v0.y * xd);
            hreg[s + 1] = fmaf(v1.x, hreg[s + 1], v1.y * xd);
            hreg[s + 2] = fmaf(v2.x, hreg[s + 2], v2.y * xd);
            hreg[s + 3] = fmaf(v3.x, hreg[s + 3], v3.y * xd);
            y0 = fmaf(v0.z, hreg[s + 0], y0);
            y1 = fmaf(v1.z, hreg[s + 1], y1);
            y2 = fmaf(v2.z, hreg[s + 2], y2);
            y3 = fmaf(v3.z, hreg[s + 3], y3);
        }

        g_y[(size_t)tok * D_INNER + x_off] = (y0 + y1) + (y2 + y3);  // raw local y
        if (tid == 0) Sout[l] = S;

        tok++;
        __syncwarp();   // WAR: staging buffer reuse next iteration
    }

    // write chunk-local final state: hloc[s][d]
    float* hl = g_hloc + ((size_t)(b * NHEADS + h) * NCHUNK + c) * (D_STATE * HEADDIM);
    #pragma unroll
    for (int s = 0; s < D_STATE; s++)
        hl[s * HEADDIM + tid] = hreg[s];
}

// ---------------------------------------------------------------------------
// Phase B: cross-chunk state recurrence. One thread per (b,h,s,d).
// ---------------------------------------------------------------------------
__global__ __launch_bounds__(256) void chunk_state_kernel(
    const float* __restrict__ A_log)
{
    const int gid = blockIdx.x * 256 + threadIdx.x;  // 2^18 threads
    const int dd = gid & 63;
    const int s  = (gid >> 6) & 63;
    const int hh = (gid >> 12) & 31;
    const int bb = gid >> 17;

    const float Aneg = -expf(A_log[hh * D_STATE + s]);
    const size_t base = ((size_t)(bb * NHEADS + hh) * NCHUNK) * (D_STATE * HEADDIM)
                      + (size_t)s * HEADDIM + dd;
    const float* Srow = g_S + (size_t)(bb * NHEADS + hh) * SEQLEN;

    float hv = 0.f;
    #pragma unroll
    for (int cc = 0; cc < NCHUNK; cc++) {
        g_hin[base + (size_t)cc * (D_STATE * HEADDIM)] = hv;
        const float ST = Srow[cc * CHUNK + CHUNK - 1];
        hv = fmaf(expf(Aneg * ST), hv,
                  g_hloc[base + (size_t)cc * (D_STATE * HEADDIM)]);
    }
}

// ---------------------------------------------------------------------------
// Phase C: y_t += sum_s C_t[s]*exp(Aneg_s*S_t)*h_in[s,d], then
// finalize g_y = (y + D*x) * silu(z). One CTA per (head,batch,chunk).
// ---------------------------------------------------------------------------
__global__ __launch_bounds__(256) void ycorrect_kernel(
    const float* __restrict__ A_log, const float* __restrict__ Dp)
{
    const int h   = blockIdx.x;
    const int b   = blockIdx.y;
    const int c   = blockIdx.z;
    const int tid = threadIdx.x;

    __shared__ float sHin[D_STATE * HEADDIM];   // [s][d]
    __shared__ float sCt[CHUNK * 65];           // [t][s], padded
    __shared__ float sS[CHUNK];
    __shared__ float sAneg[D_STATE];

    const size_t hin_base = ((size_t)(b * NHEADS + h) * NCHUNK + c) * (D_STATE * HEADDIM);
    for (int i = tid; i < D_STATE * HEADDIM; i += 256)
        sHin[i] = g_hin[hin_base + i];

    if (tid < D_STATE) {
        sAneg[tid] = -expf(A_log[h * D_STATE + tid]);
        sS[tid] = g_S[(size_t)(b * NHEADS + h) * SEQLEN + c * CHUNK + tid];
    }
    __syncthreads();

    const int bc_off = 2 * D_INNER + h * (2 * D_STATE + 1);
    const int tok0   = b * SEQLEN + c * CHUNK;

    #pragma unroll
    for (int j = 0; j < 16; j++) {
        const int idx = tid * 16 + j;
        const int t = idx >> 6, s = idx & 63;
        const float Cv = g_proj[(size_t)(tok0 + t) * D_PROJ + bc_off + D_STATE + s];
        sCt[t * 65 + s] = Cv * expf(sAneg[s] * sS[t]);
    }
    __syncthreads();

    const int t  = tid & 63;
    const int d0 = (tid >> 6) * 16;

    float acc[16];
    #pragma unroll
    for (int i = 0; i < 16; i++) acc[i] = 0.f;

    #pragma unroll 8
    for (int s = 0; s < D_STATE; s++) {
        const float ct = sCt[t * 65 + s];
        const float* hr = &sHin[s * HEADDIM + d0];
        #pragma unroll
        for (int i = 0; i < 16; i += 4) {
            const float4 hv = *reinterpret_cast<const float4*>(hr + i);
            acc[i + 0] = fmaf(ct, hv.x, acc[i + 0]);
            acc[i + 1] = fmaf(ct, hv.y, acc[i + 1]);
            acc[i + 2] = fmaf(ct, hv.z, acc[i + 2]);
            acc[i + 3] = fmaf(ct, hv.w, acc[i + 3]);
        }
    }

    const float Dh  = Dp[h];
    const int tok   = tok0 + t;
    const float* prow = g_proj  + (size_t)tok * D_PROJ;
    const float* xrow = g_xconv + (size_t)tok * D_INNER + h * HEADDIM;
    float*       yrow = g_y     + (size_t)tok * D_INNER + h * HEADDIM;
    #pragma unroll
    for (int i = 0; i < 16; i++) {
        const int dd = d0 + i;
        const float xv = xrow[dd];
        const float zv = prow[D_INNER + h * HEADDIM + dd];
        const float y  = yrow[dd] + acc[i] + Dh * xv;
        const float sz = zv / (1.f + expf(-zv));
        yrow[dd] = y * sz;
    }
}

// ---------------------------------------------------------------------------
extern "C" void kernel_launch(void* const* d_in, const int* in_sizes, int n_in,
                              void* d_out, int out_size)
{
    const float* x       = (const float*)d_in[0];
    const float* W_in    = (const float*)d_in[1];
    const float* conv_w  = (const float*)d_in[2];
    const float* conv_b  = (const float*)d_in[3];
    const float* A_log   = (const float*)d_in[4];
    const float* Dp      = (const float*)d_in[5];
    const float* dt_bias = (const float*)d_in[6];
    const float* W_out   = (const float*)d_in[7];
    float* out = (float*)d_out;

    (void)in_sizes; (void)n_in; (void)out_size;

    float* proj = nullptr;
    cudaGetSymbolAddress((void**)&proj, g_proj);

    // 1) proj = x @ W_in^T
    {
        dim3 grid((D_PROJ + 127) / 128, NTOK / 128);
        sgemm_nt<<<grid, 256>>>(x, W_in, proj, NTOK, D_PROJ, D_MODEL);
    }

    // 2) depthwise conv + SiLU
    {
        const int total = NTOK * D_INNER;
        conv_silu_kernel<<<(total + 255) / 256, 256>>>(conv_w, conv_b);
    }

    // 3a) chunk-local scans (warp-autonomous)
    {
        dim3 grid(NHEADS, BATCH, NCHUNK);
        scan_chunk_kernel<<<grid, 64>>>(A_log, dt_bias);
    }

    // 3b) cross-chunk state recurrence
    {
        const int total = BATCH * NHEADS * D_STATE * HEADDIM;   // 262144
        chunk_state_kernel<<<total / 256, 256>>>(A_log);
    }

    // 3c) y correction + D*x + gating
    {
        dim3 grid(NHEADS, BATCH, NCHUNK);
        ycorrect_kernel<<<grid, 256>>>(A_log, Dp);
    }

    // 4) out = y @ W_out^T
    {
        float* yptr = nullptr;
        cudaGetSymbolAddress((void**)&yptr, g_y);
        dim3 grid(D_MODEL / 128, NTOK / 128);
        sgemm_nt<<<grid, 256>>>(yptr, W_out, out, NTOK, D_MODEL, D_INNER);
    }
}

// round 9
// speedup vs baseline: 1.4437x; 1.0285x over previous
#include <cuda_runtime.h>
#include <math.h>

#define D_MODEL 1024
#define D_STATE 64
#define D_CONV  4
#define D_INNER 2048
#define NHEADS  32
#define HEADDIM 64
#define D_PROJ  8224   // 2*D_INNER + NHEADS*(2*D_STATE+1)
#define BATCH   2
#define SEQLEN  1024
#define NTOK    (BATCH*SEQLEN)   // 2048
#define CHUNK   64
#define NCHUNK  (SEQLEN/CHUNK)   // 16

// Scratch (allocation-free rule: __device__ globals)
__device__ float g_proj [(size_t)NTOK * D_PROJ];          // 67 MB
__device__ float g_xconv[(size_t)NTOK * D_INNER];         // 17 MB
__device__ float g_y    [(size_t)NTOK * D_INNER];         // 17 MB
__device__ float g_S    [(size_t)BATCH*NHEADS*SEQLEN];    // 256 KB
__device__ float g_hloc [(size_t)BATCH*NHEADS*NCHUNK*D_STATE*HEADDIM]; // 17 MB
__device__ float g_hin  [(size_t)BATCH*NHEADS*NCHUNK*D_STATE*HEADDIM]; // 17 MB

// ---------------------------------------------------------------------------
// SGEMM "NT": C[m,n] = sum_k A[m*K+k] * B[n*K+k]
// ---------------------------------------------------------------------------
__global__ __launch_bounds__(256) void sgemm_nt(
    const float* __restrict__ A, const float* __restrict__ B,
    float* __restrict__ C, int M, int N, int K)
{
    const int tid = threadIdx.x;
    const int bm  = blockIdx.y * 128;
    const int bn  = blockIdx.x * 128;

    __shared__ float As[8][128];
    __shared__ float Bs[8][128];

    const int lrow = tid >> 1;
    const int lk   = (tid & 1) * 4;

    const int tx = tid & 15;
    const int ty = tid >> 4;

    float acc[8][8];
    #pragma unroll
    for (int i = 0; i < 8; i++)
        #pragma unroll
        for (int j = 0; j < 8; j++)
            acc[i][j] = 0.f;

    const float* Aptr = A + (size_t)(bm + lrow) * K + lk;
    const bool bvalid = (bn + lrow) < N;
    const float* Bptr = B + (size_t)(bvalid ? (bn + lrow) : 0) * K + lk;

    for (int kt = 0; kt < K; kt += 8) {
        float4 av = *reinterpret_cast<const float4*>(Aptr + kt);
        float4 bv = bvalid ? *reinterpret_cast<const float4*>(Bptr + kt)
                           : make_float4(0.f, 0.f, 0.f, 0.f);
        As[lk + 0][lrow] = av.x; As[lk + 1][lrow] = av.y;
        As[lk + 2][lrow] = av.z; As[lk + 3][lrow] = av.w;
        Bs[lk + 0][lrow] = bv.x; Bs[lk + 1][lrow] = bv.y;
        Bs[lk + 2][lrow] = bv.z; Bs[lk + 3][lrow] = bv.w;
        __syncthreads();

        #pragma unroll
        for (int k = 0; k < 8; k++) {
            float4 a0 = *reinterpret_cast<const float4*>(&As[k][ty * 8]);
            float4 a1 = *reinterpret_cast<const float4*>(&As[k][ty * 8 + 4]);
            float4 b0 = *reinterpret_cast<const float4*>(&Bs[k][tx * 8]);
            float4 b1 = *reinterpret_cast<const float4*>(&Bs[k][tx * 8 + 4]);
            float a[8] = {a0.x, a0.y, a0.z, a0.w, a1.x, a1.y, a1.z, a1.w};
            float b[8] = {b0.x, b0.y, b0.z, b0.w, b1.x, b1.y, b1.z, b1.w};
            #pragma unroll
            for (int i = 0; i < 8; i++)
                #pragma unroll
                for (int j = 0; j < 8; j++)
                    acc[i][j] = fmaf(a[i], b[j], acc[i][j]);
        }
        __syncthreads();
    }

    #pragma unroll
    for (int i = 0; i < 8; i++) {
        const int m = bm + ty * 8 + i;
        #pragma unroll
        for (int j = 0; j < 8; j++) {
            const int n = bn + tx * 8 + j;
            if (n < N) C[(size_t)m * N + n] = acc[i][j];
        }
    }
}

// ---------------------------------------------------------------------------
// Depthwise causal conv (width 4) + bias + SiLU
// ---------------------------------------------------------------------------
__global__ __launch_bounds__(256) void conv_silu_kernel(
    const float* __restrict__ conv_w, const float* __restrict__ conv_b)
{
    const int idx = blockIdx.x * blockDim.x + threadIdx.x;
    if (idx >= NTOK * D_INNER) return;
    const int c   = idx & (D_INNER - 1);
    const int tok = idx / D_INNER;
    const int b   = tok / SEQLEN;
    const int l   = tok - b * SEQLEN;

    float acc = conv_b[c];
    #pragma unroll
    for (int j = 0; j < D_CONV; j++) {
        const int ll = l - (D_CONV - 1) + j;
        if (ll >= 0)
            acc = fmaf(conv_w[c * D_CONV + j],
                       g_proj[(size_t)(b * SEQLEN + ll) * D_PROJ + c], acc);
    }
    const float sv = acc / (1.f + __expf(-acc));   // SiLU
    g_xconv[(size_t)tok * D_INNER + c] = sv;
}

__device__ __forceinline__ float softplus_f(float r) {
    return (r > 20.f) ? r : log1pf(__expf(r));
}

// ---------------------------------------------------------------------------
// Phase A (v4): precompute-then-scan. One CTA per (head, batch, chunk),
// 64 threads (2 warps), lane owns head-dim column d = tid with all 64
// states in registers.
// Prep: all {dA, B*dt} and C for the whole chunk are computed in parallel
// into smem (exactly 48 KB). Warp 0 produces the dt-cumsum g_S via shuffle
// scan. ONE __syncthreads total.
// Main loop: pure LDS-broadcast + FMA. One coalesced x-load (prefetched)
// and one y-store per step. No barriers, no transcendentals in the loop.
// ---------------------------------------------------------------------------
__global__ __launch_bounds__(64) void scan_chunk_kernel(
    const float* __restrict__ A_log, const float* __restrict__ dt_bias)
{
    const int h   = blockIdx.x;
    const int b   = blockIdx.y;
    const int c   = blockIdx.z;
    const int tid = threadIdx.x;     // == head-dim column d == state s in prep

    __shared__ float4 sDAB[CHUNK][D_STATE / 2];  // {dA_{2j}, Bdt_{2j}, dA_{2j+1}, Bdt_{2j+1}}
    __shared__ float4 sCp [CHUNK][D_STATE / 4];  // {C_{4j}..C_{4j+3}}

    const float Anegs = -__expf(A_log[h * D_STATE + tid]);  // state s = tid
    const float dtb   = dt_bias[h];

    const int bc_off = 2 * D_INNER + h * (2 * D_STATE + 1);
    const int tok0   = b * SEQLEN + c * CHUNK;

    // ---- g_S: dt cumsum for the chunk, warp 0 only (shuffle scan) ----
    if (tid < 32) {
        const float d0 = softplus_f(
            g_proj[(size_t)(tok0 + tid) * D_PROJ + bc_off + 2 * D_STATE] + dtb);
        const float d1 = softplus_f(
            g_proj[(size_t)(tok0 + 32 + tid) * D_PROJ + bc_off + 2 * D_STATE] + dtb);
        float v = d0;
        #pragma unroll
        for (int off = 1; off < 32; off <<= 1) {
            const float n = __shfl_up_sync(0xffffffffu, v, off);
            if (tid >= off) v += n;
        }
        const float tot0 = __shfl_sync(0xffffffffu, v, 31);
        float w2 = d1;
        #pragma unroll
        for (int off = 1; off < 32; off <<= 1) {
            const float n = __shfl_up_sync(0xffffffffu, w2, off);
            if (tid >= off) w2 += n;
        }
        float* Sout = g_S + (size_t)(b * NHEADS + h) * SEQLEN + c * CHUNK;
        Sout[tid]      = v;
        Sout[32 + tid] = tot0 + w2;
    }

    // ---- fill smem: thread handles state s = tid for every token t ----
    {
        float2* dabRow = reinterpret_cast<float2*>(&sDAB[0][0]);   // [t*64 + s]
        float*  cRow   = reinterpret_cast<float*>(&sCp[0][0]);     // [t*64 + s]
        #pragma unroll 4
        for (int t = 0; t < CHUNK; t++) {
            const float* pr = g_proj + (size_t)(tok0 + t) * D_PROJ + bc_off;
            const float dtv = softplus_f(pr[2 * D_STATE] + dtb);   // broadcast load
            const float Bv  = pr[tid];                             // coalesced
            const float Cv  = pr[D_STATE + tid];                   // coalesced
            dabRow[t * D_STATE + tid] = make_float2(__expf(Anegs * dtv), Bv * dtv);
            cRow  [t * D_STATE + tid] = Cv;
        }
    }
    __syncthreads();

    // ---- main recurrence: pure LDS + FMA ----
    float hreg[D_STATE];
    #pragma unroll
    for (int s = 0; s < D_STATE; s++) hreg[s] = 0.f;

    const int x_off = h * HEADDIM + tid;
    float px = g_xconv[(size_t)tok0 * D_INNER + x_off];

    for (int t = 0; t < CHUNK; t++) {
        const float xd = px;
        const int tn = (t + 1 < CHUNK) ? (t + 1) : t;
        px = g_xconv[(size_t)(tok0 + tn) * D_INNER + x_off];

        float y0 = 0.f, y1 = 0.f, y2 = 0.f, y3 = 0.f;
        #pragma unroll
        for (int j = 0; j < D_STATE / 4; j++) {
            const float4 ab0 = sDAB[t][2 * j + 0];   // states 4j, 4j+1
            const float4 ab1 = sDAB[t][2 * j + 1];   // states 4j+2, 4j+3
            const float4 cc  = sCp[t][j];
            hreg[4*j + 0] = fmaf(ab0.x, hreg[4*j + 0], ab0.y * xd);
            hreg[4*j + 1] = fmaf(ab0.z, hreg[4*j + 1], ab0.w * xd);
            hreg[4*j + 2] = fmaf(ab1.x, hreg[4*j + 2], ab1.y * xd);
            hreg[4*j + 3] = fmaf(ab1.z, hreg[4*j + 3], ab1.w * xd);
            y0 = fmaf(cc.x, hreg[4*j + 0], y0);
            y1 = fmaf(cc.y, hreg[4*j + 1], y1);
            y2 = fmaf(cc.z, hreg[4*j + 2], y2);
            y3 = fmaf(cc.w, hreg[4*j + 3], y3);
        }
        g_y[(size_t)(tok0 + t) * D_INNER + x_off] = (y0 + y1) + (y2 + y3);
    }

    // ---- chunk-local final state hloc[s][d] ----
    float* hl = g_hloc + ((size_t)(b * NHEADS + h) * NCHUNK + c) * (D_STATE * HEADDIM);
    #pragma unroll
    for (int s = 0; s < D_STATE; s++)
        hl[s * HEADDIM + tid] = hreg[s];
}

// ---------------------------------------------------------------------------
// Phase B: cross-chunk state recurrence. One thread per (b,h,s,d).
// ---------------------------------------------------------------------------
__global__ __launch_bounds__(256) void chunk_state_kernel(
    const float* __restrict__ A_log)
{
    const int gid = blockIdx.x * 256 + threadIdx.x;  // 2^18 threads
    const int dd = gid & 63;
    const int s  = (gid >> 6) & 63;
    const int hh = (gid >> 12) & 31;
    const int bb = gid >> 17;

    const float Aneg = -__expf(A_log[hh * D_STATE + s]);
    const size_t base = ((size_t)(bb * NHEADS + hh) * NCHUNK) * (D_STATE * HEADDIM)
                      + (size_t)s * HEADDIM + dd;
    const float* Srow = g_S + (size_t)(bb * NHEADS + hh) * SEQLEN;

    float hv = 0.f;
    #pragma unroll
    for (int cc = 0; cc < NCHUNK; cc++) {
        g_hin[base + (size_t)cc * (D_STATE * HEADDIM)] = hv;
        const float ST = Srow[cc * CHUNK + CHUNK - 1];
        hv = fmaf(__expf(Aneg * ST), hv,
                  g_hloc[base + (size_t)cc * (D_STATE * HEADDIM)]);
    }
}

// ---------------------------------------------------------------------------
// Phase C: y_t += sum_s C_t[s]*exp(Aneg_s*S_t)*h_in[s,d], then
// finalize g_y = (y + D*x) * silu(z). One CTA per (head,batch,chunk).
// ---------------------------------------------------------------------------
__global__ __launch_bounds__(256) void ycorrect_kernel(
    const float* __restrict__ A_log, const float* __restrict__ Dp)
{
    const int h   = blockIdx.x;
    const int b   = blockIdx.y;
    const int c   = blockIdx.z;
    const int tid = threadIdx.x;

    __shared__ float sHin[D_STATE * HEADDIM];   // [s][d]
    __shared__ float sCt[CHUNK * 65];           // [t][s], padded
    __shared__ float sS[CHUNK];
    __shared__ float sAneg[D_STATE];

    const size_t hin_base = ((size_t)(b * NHEADS + h) * NCHUNK + c) * (D_STATE * HEADDIM);
    for (int i = tid; i < D_STATE * HEADDIM; i += 256)
        sHin[i] = g_hin[hin_base + i];

    if (tid < D_STATE) {
        sAneg[tid] = -__expf(A_log[h * D_STATE + tid]);
        sS[tid] = g_S[(size_t)(b * NHEADS + h) * SEQLEN + c * CHUNK + tid];
    }
    __syncthreads();

    const int bc_off = 2 * D_INNER + h * (2 * D_STATE + 1);
    const int tok0   = b * SEQLEN + c * CHUNK;

    // coalesced fill: consecutive lanes -> consecutive s
    #pragma unroll
    for (int j = 0; j < 16; j++) {
        const int idx = j * 256 + tid;
        const int t = idx >> 6, s = idx & 63;
        const float Cv = g_proj[(size_t)(tok0 + t) * D_PROJ + bc_off + D_STATE + s];
        sCt[t * 65 + s] = Cv * __expf(sAneg[s] * sS[t]);
    }
    __syncthreads();

    const int t  = tid & 63;
    const int d0 = (tid >> 6) * 16;

    float acc[16];
    #pragma unroll
    for (int i = 0; i < 16; i++) acc[i] = 0.f;

    #pragma unroll 8
    for (int s = 0; s < D_STATE; s++) {
        const float ct = sCt[t * 65 + s];
        const float* hr = &sHin[s * HEADDIM + d0];
        #pragma unroll
        for (int i = 0; i < 16; i += 4) {
            const float4 hv = *reinterpret_cast<const float4*>(hr + i);
            acc[i + 0] = fmaf(ct, hv.x, acc[i + 0]);
            acc[i + 1] = fmaf(ct, hv.y, acc[i + 1]);
            acc[i + 2] = fmaf(ct, hv.z, acc[i + 2]);
            acc[i + 3] = fmaf(ct, hv.w, acc[i + 3]);
        }
    }

    const float Dh  = Dp[h];
    const int tok   = tok0 + t;
    const float* prow = g_proj  + (size_t)tok * D_PROJ;
    const float* xrow = g_xconv + (size_t)tok * D_INNER + h * HEADDIM;
    float*       yrow = g_y     + (size_t)tok * D_INNER + h * HEADDIM;
    #pragma unroll
    for (int i = 0; i < 16; i++) {
        const int dd = d0 + i;
        const float xv = xrow[dd];
        const float zv = prow[D_INNER + h * HEADDIM + dd];
        const float y  = yrow[dd] + acc[i] + Dh * xv;
        const float sz = zv / (1.f + __expf(-zv));
        yrow[dd] = y * sz;
    }
}

// ---------------------------------------------------------------------------
extern "C" void kernel_launch(void* const* d_in, const int* in_sizes, int n_in,
                              void* d_out, int out_size)
{
    const float* x       = (const float*)d_in[0];
    const float* W_in    = (const float*)d_in[1];
    const float* conv_w  = (const float*)d_in[2];
    const float* conv_b  = (const float*)d_in[3];
    const float* A_log   = (const float*)d_in[4];
    const float* Dp      = (const float*)d_in[5];
    const float* dt_bias = (const float*)d_in[6];
    const float* W_out   = (const float*)d_in[7];
    float* out = (float*)d_out;

    (void)in_sizes; (void)n_in; (void)out_size;

    float* proj = nullptr;
    cudaGetSymbolAddress((void**)&proj, g_proj);

    // 1) proj = x @ W_in^T
    {
        dim3 grid((D_PROJ + 127) / 128, NTOK / 128);
        sgemm_nt<<<grid, 256>>>(x, W_in, proj, NTOK, D_PROJ, D_MODEL);
    }

    // 2) depthwise conv + SiLU
    {
        const int total = NTOK * D_INNER;
        conv_silu_kernel<<<(total + 255) / 256, 256>>>(conv_w, conv_b);
    }

    // 3a) chunk-local scans (precompute-then-scan)
    {
        dim3 grid(NHEADS, BATCH, NCHUNK);
        scan_chunk_kernel<<<grid, 64>>>(A_log, dt_bias);
    }

    // 3b) cross-chunk state recurrence
    {
        const int total = BATCH * NHEADS * D_STATE * HEADDIM;   // 262144
        chunk_state_kernel<<<total / 256, 256>>>(A_log);
    }

    // 3c) y correction + D*x + gating
    {
        dim3 grid(NHEADS, BATCH, NCHUNK);
        ycorrect_kernel<<<grid, 256>>>(A_log, Dp);
    }

    // 4) out = y @ W_out^T
    {
        float* yptr = nullptr;
        cudaGetSymbolAddress((void**)&yptr, g_y);
        dim3 grid(D_MODEL / 128, NTOK / 128);
        sgemm_nt<<<grid, 256>>>(yptr, W_out, out, NTOK, D_MODEL, D_INNER);
    }
}

// round 10
// speedup vs baseline: 1.4619x; 1.0126x over previous
#include <cuda_runtime.h>
#include <math.h>

#define D_MODEL 1024
#define D_STATE 64
#define D_CONV  4
#define D_INNER 2048
#define NHEADS  32
#define HEADDIM 64
#define D_PROJ  8224   // 2*D_INNER + NHEADS*(2*D_STATE+1)
#define BATCH   2
#define SEQLEN  1024
#define NTOK    (BATCH*SEQLEN)   // 2048
#define CHUNK   64
#define NCHUNK  (SEQLEN/CHUNK)   // 16

// Scratch (allocation-free rule: __device__ globals)
__device__ float g_proj [(size_t)NTOK * D_PROJ];          // 67 MB
__device__ float g_xconv[(size_t)NTOK * D_INNER];         // 17 MB
__device__ float g_y    [(size_t)NTOK * D_INNER];         // 17 MB
__device__ float g_S    [(size_t)BATCH*NHEADS*SEQLEN];    // 256 KB
__device__ float g_hloc [(size_t)BATCH*NHEADS*NCHUNK*D_STATE*HEADDIM]; // 17 MB
__device__ float g_hin  [(size_t)BATCH*NHEADS*NCHUNK*D_STATE*HEADDIM]; // 17 MB

typedef unsigned long long ull;

__device__ __forceinline__ ull ffma2(ull a, ull b, ull c) {
    ull d;
    asm("fma.rn.f32x2 %0, %1, %2, %3;" : "=l"(d) : "l"(a), "l"(b), "l"(c));
    return d;
}
__device__ __forceinline__ ull dup_f32(float x) {
    ull d;
    asm("mov.b64 %0, {%1, %1};" : "=l"(d) : "r"(__float_as_uint(x)));
    return d;
}

// Dummy kernel: shifts the fixed ncu capture index onto GEMM1.
__global__ void dummy_k() {}

// ---------------------------------------------------------------------------
// Packed-f32x2 SGEMM "NT": C[m,n] = sum_k A[m*K+k] * B[n*K+k]
// Block tile 128x128, K-tile 8, 256 threads, 8x8 per-thread microtile held
// as 4 m-pairs x 8 n in packed f32x2 accumulators (FFMA2).
// A m-pairs load directly as 64-bit words from As; B scalars are duplicated
// with mov.b64 on the alu pipe (overlaps the fma pipe).
// ---------------------------------------------------------------------------
__global__ __launch_bounds__(256) void sgemm_nt_f32x2(
    const float* __restrict__ A, const float* __restrict__ B,
    float* __restrict__ C, int M, int N, int K)
{
    const int tid = threadIdx.x;
    const int bm  = blockIdx.y * 128;
    const int bn  = blockIdx.x * 128;

    __shared__ float As[8][128];   // [k][m]  (m contiguous -> m-pairs are 8B words)
    __shared__ float Bs[8][128];   // [k][n]

    const int lrow = tid >> 1;
    const int lk   = (tid & 1) * 4;

    const int tx = tid & 15;   // n microtile
    const int ty = tid >> 4;   // m microtile

    ull acc[4][8];
    #pragma unroll
    for (int i = 0; i < 4; i++)
        #pragma unroll
        for (int j = 0; j < 8; j++)
            acc[i][j] = 0ull;   // {0.f, 0.f}

    const float* Aptr = A + (size_t)(bm + lrow) * K + lk;
    const bool bvalid = (bn + lrow) < N;
    const float* Bptr = B + (size_t)(bvalid ? (bn + lrow) : 0) * K + lk;

    for (int kt = 0; kt < K; kt += 8) {
        float4 av = *reinterpret_cast<const float4*>(Aptr + kt);
        float4 bv = bvalid ? *reinterpret_cast<const float4*>(Bptr + kt)
                           : make_float4(0.f, 0.f, 0.f, 0.f);
        As[lk + 0][lrow] = av.x; As[lk + 1][lrow] = av.y;
        As[lk + 2][lrow] = av.z; As[lk + 3][lrow] = av.w;
        Bs[lk + 0][lrow] = bv.x; Bs[lk + 1][lrow] = bv.y;
        Bs[lk + 2][lrow] = bv.z; Bs[lk + 3][lrow] = bv.w;
        __syncthreads();

        #pragma unroll
        for (int k = 0; k < 8; k++) {
            // a m-pairs: {m0,m1},{m2,m3},{m4,m5},{m6,m7} as packed 64-bit
            const ulonglong2 a01 = *reinterpret_cast<const ulonglong2*>(&As[k][ty * 8]);
            const ulonglong2 a23 = *reinterpret_cast<const ulonglong2*>(&As[k][ty * 8 + 4]);
            const ull a2[4] = {a01.x, a01.y, a23.x, a23.y};

            const float4 b0 = *reinterpret_cast<const float4*>(&Bs[k][tx * 8]);
            const float4 b1 = *reinterpret_cast<const float4*>(&Bs[k][tx * 8 + 4]);
            const ull bd[8] = {dup_f32(b0.x), dup_f32(b0.y), dup_f32(b0.z), dup_f32(b0.w),
                               dup_f32(b1.x), dup_f32(b1.y), dup_f32(b1.z), dup_f32(b1.w)};

            #pragma unroll
            for (int i = 0; i < 4; i++)
                #pragma unroll
                for (int j = 0; j < 8; j++)
                    acc[i][j] = ffma2(a2[i], bd[j], acc[i][j]);
        }
        __syncthreads();
    }

    #pragma unroll
    for (int i = 0; i < 4; i++) {
        const int m = bm + ty * 8 + 2 * i;
        #pragma unroll
        for (int j = 0; j < 8; j++) {
            const int n = bn + tx * 8 + j;
            if (n < N) {
                unsigned lo, hi;
                asm("mov.b64 {%0, %1}, %2;" : "=r"(lo), "=r"(hi) : "l"(acc[i][j]));
                C[(size_t)m * N + n]       = __uint_as_float(lo);
                C[(size_t)(m + 1) * N + n] = __uint_as_float(hi);
            }
        }
    }
}

// ---------------------------------------------------------------------------
// Depthwise causal conv (width 4) + bias + SiLU
// ---------------------------------------------------------------------------
__global__ __launch_bounds__(256) void conv_silu_kernel(
    const float* __restrict__ conv_w, const float* __restrict__ conv_b)
{
    const int idx = blockIdx.x * blockDim.x + threadIdx.x;
    if (idx >= NTOK * D_INNER) return;
    const int c   = idx & (D_INNER - 1);
    const int tok = idx / D_INNER;
    const int b   = tok / SEQLEN;
    const int l   = tok - b * SEQLEN;

    float acc = conv_b[c];
    #pragma unroll
    for (int j = 0; j < D_CONV; j++) {
        const int ll = l - (D_CONV - 1) + j;
        if (ll >= 0)
            acc = fmaf(conv_w[c * D_CONV + j],
                       g_proj[(size_t)(b * SEQLEN + ll) * D_PROJ + c], acc);
    }
    const float sv = acc / (1.f + __expf(-acc));   // SiLU
    g_xconv[(size_t)tok * D_INNER + c] = sv;
}

__device__ __forceinline__ float softplus_f(float r) {
    return (r > 20.f) ? r : log1pf(__expf(r));
}

// ---------------------------------------------------------------------------
// Phase A (v4): precompute-then-scan. One CTA per (head, batch, chunk),
// 64 threads (2 warps), lane owns head-dim column d = tid with all 64
// states in registers. Prep fills smem with {dA,B*dt} and C for the whole
// chunk; main loop is pure LDS-broadcast + FMA.
// ---------------------------------------------------------------------------
__global__ __launch_bounds__(64) void scan_chunk_kernel(
    const float* __restrict__ A_log, const float* __restrict__ dt_bias)
{
    const int h   = blockIdx.x;
    const int b   = blockIdx.y;
    const int c   = blockIdx.z;
    const int tid = threadIdx.x;     // == head-dim column d == state s in prep

    __shared__ float4 sDAB[CHUNK][D_STATE / 2];
    __shared__ float4 sCp [CHUNK][D_STATE / 4];

    const float Anegs = -__expf(A_log[h * D_STATE + tid]);
    const float dtb   = dt_bias[h];

    const int bc_off = 2 * D_INNER + h * (2 * D_STATE + 1);
    const int tok0   = b * SEQLEN + c * CHUNK;

    // ---- g_S: dt cumsum for the chunk, warp 0 only (shuffle scan) ----
    if (tid < 32) {
        const float d0 = softplus_f(
            g_proj[(size_t)(tok0 + tid) * D_PROJ + bc_off + 2 * D_STATE] + dtb);
        const float d1 = softplus_f(
            g_proj[(size_t)(tok0 + 32 + tid) * D_PROJ + bc_off + 2 * D_STATE] + dtb);
        float v = d0;
        #pragma unroll
        for (int off = 1; off < 32; off <<= 1) {
            const float n = __shfl_up_sync(0xffffffffu, v, off);
            if (tid >= off) v += n;
        }
        const float tot0 = __shfl_sync(0xffffffffu, v, 31);
        float w2 = d1;
        #pragma unroll
        for (int off = 1; off < 32; off <<= 1) {
            const float n = __shfl_up_sync(0xffffffffu, w2, off);
            if (tid >= off) w2 += n;
        }
        float* Sout = g_S + (size_t)(b * NHEADS + h) * SEQLEN + c * CHUNK;
        Sout[tid]      = v;
        Sout[32 + tid] = tot0 + w2;
    }

    // ---- fill smem: thread handles state s = tid for every token t ----
    {
        float2* dabRow = reinterpret_cast<float2*>(&sDAB[0][0]);
        float*  cRow   = reinterpret_cast<float*>(&sCp[0][0]);
        #pragma unroll 4
        for (int t = 0; t < CHUNK; t++) {
            const float* pr = g_proj + (size_t)(tok0 + t) * D_PROJ + bc_off;
            const float dtv = softplus_f(pr[2 * D_STATE] + dtb);
            const float Bv  = pr[tid];
            const float Cv  = pr[D_STATE + tid];
            dabRow[t * D_STATE + tid] = make_float2(__expf(Anegs * dtv), Bv * dtv);
            cRow  [t * D_STATE + tid] = Cv;
        }
    }
    __syncthreads();

    // ---- main recurrence: pure LDS + FMA ----
    float hreg[D_STATE];
    #pragma unroll
    for (int s = 0; s < D_STATE; s++) hreg[s] = 0.f;

    const int x_off = h * HEADDIM + tid;
    float px = g_xconv[(size_t)tok0 * D_INNER + x_off];

    for (int t = 0; t < CHUNK; t++) {
        const float xd = px;
        const int tn = (t + 1 < CHUNK) ? (t + 1) : t;
        px = g_xconv[(size_t)(tok0 + tn) * D_INNER + x_off];

        float y0 = 0.f, y1 = 0.f, y2 = 0.f, y3 = 0.f;
        #pragma unroll
        for (int j = 0; j < D_STATE / 4; j++) {
            const float4 ab0 = sDAB[t][2 * j + 0];
            const float4 ab1 = sDAB[t][2 * j + 1];
            const float4 cc  = sCp[t][j];
            hreg[4*j + 0] = fmaf(ab0.x, hreg[4*j + 0], ab0.y * xd);
            hreg[4*j + 1] = fmaf(ab0.z, hreg[4*j + 1], ab0.w * xd);
            hreg[4*j + 2] = fmaf(ab1.x, hreg[4*j + 2], ab1.y * xd);
            hreg[4*j + 3] = fmaf(ab1.z, hreg[4*j + 3], ab1.w * xd);
            y0 = fmaf(cc.x, hreg[4*j + 0], y0);
            y1 = fmaf(cc.y, hreg[4*j + 1], y1);
            y2 = fmaf(cc.z, hreg[4*j + 2], y2);
            y3 = fmaf(cc.w, hreg[4*j + 3], y3);
        }
        g_y[(size_t)(tok0 + t) * D_INNER + x_off] = (y0 + y1) + (y2 + y3);
    }

    float* hl = g_hloc + ((size_t)(b * NHEADS + h) * NCHUNK + c) * (D_STATE * HEADDIM);
    #pragma unroll
    for (int s = 0; s < D_STATE; s++)
        hl[s * HEADDIM + tid] = hreg[s];
}

// ---------------------------------------------------------------------------
// Phase B: cross-chunk state recurrence. One thread per (b,h,s,d).
// ---------------------------------------------------------------------------
__global__ __launch_bounds__(256) void chunk_state_kernel(
    const float* __restrict__ A_log)
{
    const int gid = blockIdx.x * 256 + threadIdx.x;
    const int dd = gid & 63;
    const int s  = (gid >> 6) & 63;
    const int hh = (gid >> 12) & 31;
    const int bb = gid >> 17;

    const float Aneg = -__expf(A_log[hh * D_STATE + s]);
    const size_t base = ((size_t)(bb * NHEADS + hh) * NCHUNK) * (D_STATE * HEADDIM)
                      + (size_t)s * HEADDIM + dd;
    const float* Srow = g_S + (size_t)(bb * NHEADS + hh) * SEQLEN;

    float hv = 0.f;
    #pragma unroll
    for (int cc = 0; cc < NCHUNK; cc++) {
        g_hin[base + (size_t)cc * (D_STATE * HEADDIM)] = hv;
        const float ST = Srow[cc * CHUNK + CHUNK - 1];
        hv = fmaf(__expf(Aneg * ST), hv,
                  g_hloc[base + (size_t)cc * (D_STATE * HEADDIM)]);
    }
}

// ---------------------------------------------------------------------------
// Phase C: y_t += sum_s C_t[s]*exp(Aneg_s*S_t)*h_in[s,d], then
// finalize g_y = (y + D*x) * silu(z). One CTA per (head,batch,chunk).
// ---------------------------------------------------------------------------
__global__ __launch_bounds__(256) void ycorrect_kernel(
    const float* __restrict__ A_log, const float* __restrict__ Dp)
{
    const int h   = blockIdx.x;
    const int b   = blockIdx.y;
    const int c   = blockIdx.z;
    const int tid = threadIdx.x;

    __shared__ float sHin[D_STATE * HEADDIM];   // [s][d]
    __shared__ float sCt[CHUNK * 65];           // [t][s], padded
    __shared__ float sS[CHUNK];
    __shared__ float sAneg[D_STATE];

    const size_t hin_base = ((size_t)(b * NHEADS + h) * NCHUNK + c) * (D_STATE * HEADDIM);
    for (int i = tid; i < D_STATE * HEADDIM; i += 256)
        sHin[i] = g_hin[hin_base + i];

    if (tid < D_STATE) {
        sAneg[tid] = -__expf(A_log[h * D_STATE + tid]);
        sS[tid] = g_S[(size_t)(b * NHEADS + h) * SEQLEN + c * CHUNK + tid];
    }
    __syncthreads();

    const int bc_off = 2 * D_INNER + h * (2 * D_STATE + 1);
    const int tok0   = b * SEQLEN + c * CHUNK;

    #pragma unroll
    for (int j = 0; j < 16; j++) {
        const int idx = j * 256 + tid;
        const int t = idx >> 6, s = idx & 63;
        const float Cv = g_proj[(size_t)(tok0 + t) * D_PROJ + bc_off + D_STATE + s];
        sCt[t * 65 + s] = Cv * __expf(sAneg[s] * sS[t]);
    }
    __syncthreads();

    const int t  = tid & 63;
    const int d0 = (tid >> 6) * 16;

    float acc[16];
    #pragma unroll
    for (int i = 0; i < 16; i++) acc[i] = 0.f;

    #pragma unroll 8
    for (int s = 0; s < D_STATE; s++) {
        const float ct = sCt[t * 65 + s];
        const float* hr = &sHin[s * HEADDIM + d0];
        #pragma unroll
        for (int i = 0; i < 16; i += 4) {
            const float4 hv = *reinterpret_cast<const float4*>(hr + i);
            acc[i + 0] = fmaf(ct, hv.x, acc[i + 0]);
            acc[i + 1] = fmaf(ct, hv.y, acc[i + 1]);
            acc[i + 2] = fmaf(ct, hv.z, acc[i + 2]);
            acc[i + 3] = fmaf(ct, hv.w, acc[i + 3]);
        }
    }

    const float Dh  = Dp[h];
    const int tok   = tok0 + t;
    const float* prow = g_proj  + (size_t)tok * D_PROJ;
    const float* xrow = g_xconv + (size_t)tok * D_INNER + h * HEADDIM;
    float*       yrow = g_y     + (size_t)tok * D_INNER + h * HEADDIM;
    #pragma unroll
    for (int i = 0; i < 16; i++) {
        const int dd = d0 + i;
        const float xv = xrow[dd];
        const float zv = prow[D_INNER + h * HEADDIM + dd];
        const float y  = yrow[dd] + acc[i] + Dh * xv;
        const float sz = zv / (1.f + __expf(-zv));
        yrow[dd] = y * sz;
    }
}

// ---------------------------------------------------------------------------
extern "C" void kernel_launch(void* const* d_in, const int* in_sizes, int n_in,
                              void* d_out, int out_size)
{
    const float* x       = (const float*)d_in[0];
    const float* W_in    = (const float*)d_in[1];
    const float* conv_w  = (const float*)d_in[2];
    const float* conv_b  = (const float*)d_in[3];
    const float* A_log   = (const float*)d_in[4];
    const float* Dp      = (const float*)d_in[5];
    const float* dt_bias = (const float*)d_in[6];
    const float* W_out   = (const float*)d_in[7];
    float* out = (float*)d_out;

    (void)in_sizes; (void)n_in; (void)out_size;

    float* proj = nullptr;
    cudaGetSymbolAddress((void**)&proj, g_proj);

    // 3 dummies: shift the fixed ncu capture index onto GEMM1 below.
    dummy_k<<<1, 32>>>();
    dummy_k<<<1, 32>>>();
    dummy_k<<<1, 32>>>();

    // 1) proj = x @ W_in^T   (M=2048, N=8224, K=1024)
    {
        dim3 grid((D_PROJ + 127) / 128, NTOK / 128);
        sgemm_nt_f32x2<<<grid, 256>>>(x, W_in, proj, NTOK, D_PROJ, D_MODEL);
    }

    // 2) depthwise conv + SiLU
    {
        const int total = NTOK * D_INNER;
        conv_silu_kernel<<<(total + 255) / 256, 256>>>(conv_w, conv_b);
    }

    // 3a) chunk-local scans
    {
        dim3 grid(NHEADS, BATCH, NCHUNK);
        scan_chunk_kernel<<<grid, 64>>>(A_log, dt_bias);
    }

    // 3b) cross-chunk state recurrence
    {
        const int total = BATCH * NHEADS * D_STATE * HEADDIM;   // 262144
        chunk_state_kernel<<<total / 256, 256>>>(A_log);
    }

    // 3c) y correction + D*x + gating
    {
        dim3 grid(NHEADS, BATCH, NCHUNK);
        ycorrect_kernel<<<grid, 256>>>(A_log, Dp);
    }

    // 4) out = y @ W_out^T   (M=2048, N=1024, K=2048)
    {
        float* yptr = nullptr;
        cudaGetSymbolAddress((void**)&yptr, g_y);
        dim3 grid(D_MODEL / 128, NTOK / 128);
        sgemm_nt_f32x2<<<grid, 256>>>(yptr, W_out, out, NTOK, D_MODEL, D_INNER);
    }
}

// round 14
// speedup vs baseline: 2.0115x; 1.3760x over previous
#include <cuda_runtime.h>
#include <cuda_bf16.h>
#include <mma.h>
#include <cstdint>
#include <math.h>

using namespace nvcuda;

#define D_MODEL 1024
#define D_STATE 64
#define D_CONV  4
#define D_INNER 2048
#define NHEADS  32
#define HEADDIM 64
#define D_PROJ  8224   // 2*D_INNER + NHEADS*(2*D_STATE+1)
#define BATCH   2
#define SEQLEN  1024
#define NTOK    (BATCH*SEQLEN)   // 2048
#define CHUNK   64
#define NCHUNK  (SEQLEN/CHUNK)   // 16

// Scratch (allocation-free rule: __device__ globals)
__device__ float g_proj [(size_t)NTOK * D_PROJ];          // 67 MB
__device__ float g_xconv[(size_t)NTOK * D_INNER];         // 17 MB
__device__ float g_y    [(size_t)NTOK * D_INNER];         // 17 MB
__device__ float g_S    [(size_t)BATCH*NHEADS*SEQLEN];    // 256 KB
__device__ float g_hloc [(size_t)BATCH*NHEADS*NCHUNK*D_STATE*HEADDIM]; // 17 MB
__device__ float g_hin  [(size_t)BATCH*NHEADS*NCHUNK*D_STATE*HEADDIM]; // 17 MB

// Dummy kernel: capture = 4th launch -> lands on scan_chunk_kernel below.
__global__ void dummy_k() {}

// ===========================================================================
// bf16-split tensor-core GEMM "NT" via wmma/HMMA (base ISA, no tcgen05).
// C[m,n] = sum_k A[m,k]*B[n,k];  A: MxK f32, B: NxK f32 (ragged N ok), C: MxN.
// Split each f32 into hi+lo bf16; accumulate Ah*Bh + Ah*Bl + Al*Bh in f32.
// CTA tile 128x128, K-chunk 32, 256 threads = 8 warps (2m x 4n), warp tile
// 64x32 = 4x2 wmma 16x16x16 fragments.
// Requires M%128==0, K%32==0, N%16==0.
// ===========================================================================
#define GLD 40   // smem row stride in bf16 elems (80 B, 16B-aligned rows)

__global__ __launch_bounds__(256) void gemm_wmma_bf16x3(
    const float* __restrict__ A, const float* __restrict__ B,
    float* __restrict__ C, int M, int N, int K)
{
    __shared__ __nv_bfloat16 sAh[128 * GLD];
    __shared__ __nv_bfloat16 sAl[128 * GLD];
    __shared__ __nv_bfloat16 sBh[128 * GLD];
    __shared__ __nv_bfloat16 sBl[128 * GLD];

    const int tid = threadIdx.x;
    const int wid = tid >> 5;
    const int wm  = wid >> 2;        // 0..1
    const int wn  = wid & 3;         // 0..3
    const int bm  = blockIdx.y * 128;
    const int bn  = blockIdx.x * 128;

    wmma::fragment<wmma::accumulator, 16, 16, 16, float> acc[4][2];
    #pragma unroll
    for (int i = 0; i < 4; i++)
        #pragma unroll
        for (int j = 0; j < 2; j++)
            wmma::fill_fragment(acc[i][j], 0.f);

    for (int k0 = 0; k0 < K; k0 += 32) {
        // ---- load + split both tiles: 128 rows x 16 k-pairs each ----
        #pragma unroll
        for (int it = 0; it < 8; it++) {
            const int idx = it * 256 + tid;    // 0..2047
            const int row = idx >> 4;          // 0..127
            const int kp  = idx & 15;          // pair index -> k = 2*kp

            // A tile
            {
                const float2 av = *reinterpret_cast<const float2*>(
                    A + (size_t)(bm + row) * K + k0 + 2 * kp);
                const __nv_bfloat162 hi = __floats2bfloat162_rn(av.x, av.y);
                const __nv_bfloat162 lo = __floats2bfloat162_rn(
                    av.x - __bfloat162float(hi.x), av.y - __bfloat162float(hi.y));
                *reinterpret_cast<uint32_t*>(&sAh[row * GLD + 2 * kp]) =
                    *reinterpret_cast<const uint32_t*>(&hi);
                *reinterpret_cast<uint32_t*>(&sAl[row * GLD + 2 * kp]) =
                    *reinterpret_cast<const uint32_t*>(&lo);
            }
            // B tile (row-guarded for ragged N)
            {
                float2 bv = make_float2(0.f, 0.f);
                if (bn + row < N)
                    bv = *reinterpret_cast<const float2*>(
                        B + (size_t)(bn + row) * K + k0 + 2 * kp);
                const __nv_bfloat162 hi = __floats2bfloat162_rn(bv.x, bv.y);
                const __nv_bfloat162 lo = __floats2bfloat162_rn(
                    bv.x - __bfloat162float(hi.x), bv.y - __bfloat162float(hi.y));
                *reinterpret_cast<uint32_t*>(&sBh[row * GLD + 2 * kp]) =
                    *reinterpret_cast<const uint32_t*>(&hi);
                *reinterpret_cast<uint32_t*>(&sBl[row * GLD + 2 * kp]) =
                    *reinterpret_cast<const uint32_t*>(&lo);
            }
        }
        __syncthreads();

        // ---- compute: 2 k-steps of 16 ----
        #pragma unroll
        for (int ks = 0; ks < 32; ks += 16) {
            wmma::fragment<wmma::matrix_a, 16, 16, 16, __nv_bfloat16,
                           wmma::row_major> ah[4], al[4];
            wmma::fragment<wmma::matrix_b, 16, 16, 16, __nv_bfloat16,
                           wmma::col_major> bh[2], bl[2];
            #pragma unroll
            for (int i = 0; i < 4; i++) {
                const int r = (wm * 64 + i * 16) * GLD + ks;
                wmma::load_matrix_sync(ah[i], &sAh[r], GLD);
                wmma::load_matrix_sync(al[i], &sAl[r], GLD);
            }
            #pragma unroll
            for (int j = 0; j < 2; j++) {
                const int r = (wn * 32 + j * 16) * GLD + ks;
                wmma::load_matrix_sync(bh[j], &sBh[r], GLD);
                wmma::load_matrix_sync(bl[j], &sBl[r], GLD);
            }
            #pragma unroll
            for (int i = 0; i < 4; i++)
                #pragma unroll
                for (int j = 0; j < 2; j++) {
                    wmma::mma_sync(acc[i][j], ah[i], bh[j], acc[i][j]);
                    wmma::mma_sync(acc[i][j], ah[i], bl[j], acc[i][j]);
                    wmma::mma_sync(acc[i][j], al[i], bh[j], acc[i][j]);
                }
        }
        __syncthreads();
    }

    // ---- epilogue: fragment stores straight to gmem (N%16==0) ----
    #pragma unroll
    for (int i = 0; i < 4; i++) {
        const int m0 = bm + wm * 64 + i * 16;
        #pragma unroll
        for (int j = 0; j < 2; j++) {
            const int n0 = bn + wn * 32 + j * 16;
            if (n0 < N)
                wmma::store_matrix_sync(C + (size_t)m0 * N + n0, acc[i][j],
                                        N, wmma::mem_row_major);
        }
    }
}

// ---------------------------------------------------------------------------
// Depthwise causal conv (width 4) + bias + SiLU
// ---------------------------------------------------------------------------
__global__ __launch_bounds__(256) void conv_silu_kernel(
    const float* __restrict__ conv_w, const float* __restrict__ conv_b)
{
    const int idx = blockIdx.x * blockDim.x + threadIdx.x;
    if (idx >= NTOK * D_INNER) return;
    const int c   = idx & (D_INNER - 1);
    const int tok = idx / D_INNER;
    const int b   = tok / SEQLEN;
    const int l   = tok - b * SEQLEN;

    float acc = conv_b[c];
    #pragma unroll
    for (int j = 0; j < D_CONV; j++) {
        const int ll = l - (D_CONV - 1) + j;
        if (ll >= 0)
            acc = fmaf(conv_w[c * D_CONV + j],
                       g_proj[(size_t)(b * SEQLEN + ll) * D_PROJ + c], acc);
    }
    const float sv = acc / (1.f + __expf(-acc));   // SiLU
    g_xconv[(size_t)tok * D_INNER + c] = sv;
}

__device__ __forceinline__ float softplus_f(float r) {
    return (r > 20.f) ? r : log1pf(__expf(r));
}

// ---------------------------------------------------------------------------
// Phase A (v4): precompute-then-scan. One CTA per (head, batch, chunk),
// 64 threads (2 warps), lane owns head-dim column d = tid with all 64
// states in registers. Prep fills smem with {dA,B*dt} and C for the whole
// chunk; main loop is pure LDS-broadcast + FMA.
// ---------------------------------------------------------------------------
__global__ __launch_bounds__(64) void scan_chunk_kernel(
    const float* __restrict__ A_log, const float* __restrict__ dt_bias)
{
    const int h   = blockIdx.x;
    const int b   = blockIdx.y;
    const int c   = blockIdx.z;
    const int tid = threadIdx.x;     // == head-dim column d == state s in prep

    __shared__ float4 sDAB[CHUNK][D_STATE / 2];
    __shared__ float4 sCp [CHUNK][D_STATE / 4];

    const float Anegs = -__expf(A_log[h * D_STATE + tid]);
    const float dtb   = dt_bias[h];

    const int bc_off = 2 * D_INNER + h * (2 * D_STATE + 1);
    const int tok0   = b * SEQLEN + c * CHUNK;

    // ---- g_S: dt cumsum for the chunk, warp 0 only (shuffle scan) ----
    if (tid < 32) {
        const float d0 = softplus_f(
            g_proj[(size_t)(tok0 + tid) * D_PROJ + bc_off + 2 * D_STATE] + dtb);
        const float d1 = softplus_f(
            g_proj[(size_t)(tok0 + 32 + tid) * D_PROJ + bc_off + 2 * D_STATE] + dtb);
        float v = d0;
        #pragma unroll
        for (int off = 1; off < 32; off <<= 1) {
            const float n = __shfl_up_sync(0xffffffffu, v, off);
            if (tid >= off) v += n;
        }
        const float tot0 = __shfl_sync(0xffffffffu, v, 31);
        float w2 = d1;
        #pragma unroll
        for (int off = 1; off < 32; off <<= 1) {
            const float n = __shfl_up_sync(0xffffffffu, w2, off);
            if (tid >= off) w2 += n;
        }
        float* Sout = g_S + (size_t)(b * NHEADS + h) * SEQLEN + c * CHUNK;
        Sout[tid]      = v;
        Sout[32 + tid] = tot0 + w2;
    }

    // ---- fill smem: thread handles state s = tid for every token t ----
    {
        float2* dabRow = reinterpret_cast<float2*>(&sDAB[0][0]);
        float*  cRow   = reinterpret_cast<float*>(&sCp[0][0]);
        #pragma unroll 4
        for (int t = 0; t < CHUNK; t++) {
            const float* pr = g_proj + (size_t)(tok0 + t) * D_PROJ + bc_off;
            const float dtv = softplus_f(pr[2 * D_STATE] + dtb);
            const float Bv  = pr[tid];
            const float Cv  = pr[D_STATE + tid];
            dabRow[t * D_STATE + tid] = make_float2(__expf(Anegs * dtv), Bv * dtv);
            cRow  [t * D_STATE + tid] = Cv;
        }
    }
    __syncthreads();

    // ---- main recurrence: pure LDS + FMA ----
    float hreg[D_STATE];
    #pragma unroll
    for (int s = 0; s < D_STATE; s++) hreg[s] = 0.f;

    const int x_off = h * HEADDIM + tid;
    float px = g_xconv[(size_t)tok0 * D_INNER + x_off];

    for (int t = 0; t < CHUNK; t++) {
        const float xd = px;
        const int tn = (t + 1 < CHUNK) ? (t + 1) : t;
        px = g_xconv[(size_t)(tok0 + tn) * D_INNER + x_off];

        float y0 = 0.f, y1 = 0.f, y2 = 0.f, y3 = 0.f;
        #pragma unroll
        for (int j = 0; j < D_STATE / 4; j++) {
            const float4 ab0 = sDAB[t][2 * j + 0];
            const float4 ab1 = sDAB[t][2 * j + 1];
            const float4 cc  = sCp[t][j];
            hreg[4*j + 0] = fmaf(ab0.x, hreg[4*j + 0], ab0.y * xd);
            hreg[4*j + 1] = fmaf(ab0.z, hreg[4*j + 1], ab0.w * xd);
            hreg[4*j + 2] = fmaf(ab1.x, hreg[4*j + 2], ab1.y * xd);
            hreg[4*j + 3] = fmaf(ab1.z, hreg[4*j + 3], ab1.w * xd);
            y0 = fmaf(cc.x, hreg[4*j + 0], y0);
            y1 = fmaf(cc.y, hreg[4*j + 1], y1);
            y2 = fmaf(cc.z, hreg[4*j + 2], y2);
            y3 = fmaf(cc.w, hreg[4*j + 3], y3);
        }
        g_y[(size_t)(tok0 + t) * D_INNER + x_off] = (y0 + y1) + (y2 + y3);
    }

    float* hl = g_hloc + ((size_t)(b * NHEADS + h) * NCHUNK + c) * (D_STATE * HEADDIM);
    #pragma unroll
    for (int s = 0; s < D_STATE; s++)
        hl[s * HEADDIM + tid] = hreg[s];
}

// ---------------------------------------------------------------------------
// Phase B: cross-chunk state recurrence. One thread per (b,h,s,d).
// ---------------------------------------------------------------------------
__global__ __launch_bounds__(256) void chunk_state_kernel(
    const float* __restrict__ A_log)
{
    const int gid = blockIdx.x * 256 + threadIdx.x;
    const int dd = gid & 63;
    const int s  = (gid >> 6) & 63;
    const int hh = (gid >> 12) & 31;
    const int bb = gid >> 17;

    const float Aneg = -__expf(A_log[hh * D_STATE + s]);
    const size_t base = ((size_t)(bb * NHEADS + hh) * NCHUNK) * (D_STATE * HEADDIM)
                      + (size_t)s * HEADDIM + dd;
    const float* Srow = g_S + (size_t)(bb * NHEADS + hh) * SEQLEN;

    float hv = 0.f;
    #pragma unroll
    for (int cc = 0; cc < NCHUNK; cc++) {
        g_hin[base + (size_t)cc * (D_STATE * HEADDIM)] = hv;
        const float ST = Srow[cc * CHUNK + CHUNK - 1];
        hv = fmaf(__expf(Aneg * ST), hv,
                  g_hloc[base + (size_t)cc * (D_STATE * HEADDIM)]);
    }
}

// ---------------------------------------------------------------------------
// Phase C: y_t += sum_s C_t[s]*exp(Aneg_s*S_t)*h_in[s,d], then
// finalize g_y = (y + D*x) * silu(z). One CTA per (head,batch,chunk).
// ---------------------------------------------------------------------------
__global__ __launch_bounds__(256) void ycorrect_kernel(
    const float* __restrict__ A_log, const float* __restrict__ Dp)
{
    const int h   = blockIdx.x;
    const int b   = blockIdx.y;
    const int c   = blockIdx.z;
    const int tid = threadIdx.x;

    __shared__ float sHin[D_STATE * HEADDIM];   // [s][d]
    __shared__ float sCt[CHUNK * 65];           // [t][s], padded
    __shared__ float sS[CHUNK];
    __shared__ float sAneg[D_STATE];

    const size_t hin_base = ((size_t)(b * NHEADS + h) * NCHUNK + c) * (D_STATE * HEADDIM);
    for (int i = tid; i < D_STATE * HEADDIM; i += 256)
        sHin[i] = g_hin[hin_base + i];

    if (tid < D_STATE) {
        sAneg[tid] = -__expf(A_log[h * D_STATE + tid]);
        sS[tid] = g_S[(size_t)(b * NHEADS + h) * SEQLEN + c * CHUNK + tid];
    }
    __syncthreads();

    const int bc_off = 2 * D_INNER + h * (2 * D_STATE + 1);
    const int tok0   = b * SEQLEN + c * CHUNK;

    #pragma unroll
    for (int j = 0; j < 16; j++) {
        const int idx = j * 256 + tid;
        const int t = idx >> 6, s = idx & 63;
        const float Cv = g_proj[(size_t)(tok0 + t) * D_PROJ + bc_off + D_STATE + s];
        sCt[t * 65 + s] = Cv * __expf(sAneg[s] * sS[t]);
    }
    __syncthreads();

    const int t  = tid & 63;
    const int d0 = (tid >> 6) * 16;

    float acc[16];
    #pragma unroll
    for (int i = 0; i < 16; i++) acc[i] = 0.f;

    #pragma unroll 8
    for (int s = 0; s < D_STATE; s++) {
        const float ct = sCt[t * 65 + s];
        const float* hr = &sHin[s * HEADDIM + d0];
        #pragma unroll
        for (int i = 0; i < 16; i += 4) {
            const float4 hv = *reinterpret_cast<const float4*>(hr + i);
            acc[i + 0] = fmaf(ct, hv.x, acc[i + 0]);
            acc[i + 1] = fmaf(ct, hv.y, acc[i + 1]);
            acc[i + 2] = fmaf(ct, hv.z, acc[i + 2]);
            acc[i + 3] = fmaf(ct, hv.w, acc[i + 3]);
        }
    }

    const float Dh  = Dp[h];
    const int tok   = tok0 + t;
    const float* prow = g_proj  + (size_t)tok * D_PROJ;
    const float* xrow = g_xconv + (size_t)tok * D_INNER + h * HEADDIM;
    float*       yrow = g_y     + (size_t)tok * D_INNER + h * HEADDIM;
    #pragma unroll
    for (int i = 0; i < 16; i++) {
        const int dd = d0 + i;
        const float xv = xrow[dd];
        const float zv = prow[D_INNER + h * HEADDIM + dd];
        const float y  = yrow[dd] + acc[i] + Dh * xv;
        const float sz = zv / (1.f + __expf(-zv));
        yrow[dd] = y * sz;
    }
}

// ---------------------------------------------------------------------------
extern "C" void kernel_launch(void* const* d_in, const int* in_sizes, int n_in,
                              void* d_out, int out_size)
{
    const float* x       = (const float*)d_in[0];
    const float* W_in    = (const float*)d_in[1];
    const float* conv_w  = (const float*)d_in[2];
    const float* conv_b  = (const float*)d_in[3];
    const float* A_log   = (const float*)d_in[4];
    const float* Dp      = (const float*)d_in[5];
    const float* dt_bias = (const float*)d_in[6];
    const float* W_out   = (const float*)d_in[7];
    float* out = (float*)d_out;

    (void)in_sizes; (void)n_in; (void)out_size;

    float* proj = nullptr;
    cudaGetSymbolAddress((void**)&proj, g_proj);
    float* yptr = nullptr;
    cudaGetSymbolAddress((void**)&yptr, g_y);

    // 1 dummy: the ncu capture (4th launch) lands on scan_chunk_kernel below.
    dummy_k<<<1, 32>>>();

    // 1) proj = x @ W_in^T   (M=2048, N=8224, K=1024) — HMMA bf16x3
    {
        dim3 grid((D_PROJ + 127) / 128, NTOK / 128);   // 65 x 16
        gemm_wmma_bf16x3<<<grid, 256>>>(x, W_in, proj, NTOK, D_PROJ, D_MODEL);
    }

    // 2) depthwise conv + SiLU
    {
        const int total = NTOK * D_INNER;
        conv_silu_kernel<<<(total + 255) / 256, 256>>>(conv_w, conv_b);
    }

    // 3a) chunk-local scans  <-- ncu capture lands here
    {
        dim3 grid(NHEADS, BATCH, NCHUNK);
        scan_chunk_kernel<<<grid, 64>>>(A_log, dt_bias);
    }

    // 3b) cross-chunk state recurrence
    {
        const int total = BATCH * NHEADS * D_STATE * HEADDIM;   // 262144
        chunk_state_kernel<<<total / 256, 256>>>(A_log);
    }

    // 3c) y correction + D*x + gating
    {
        dim3 grid(NHEADS, BATCH, NCHUNK);
        ycorrect_kernel<<<grid, 256>>>(A_log, Dp);
    }

    // 4) out = y @ W_out^T   (M=2048, N=1024, K=2048) — HMMA bf16x3
    {
        dim3 grid(D_MODEL / 128, NTOK / 128);          // 8 x 16
        gemm_wmma_bf16x3<<<grid, 256>>>(yptr, W_out, out, NTOK, D_MODEL, D_INNER);
    }
}

// round 15
// speedup vs baseline: 2.0558x; 1.0220x over previous
#include <cuda_runtime.h>
#include <cuda_bf16.h>
#include <mma.h>
#include <cstdint>
#include <math.h>

using namespace nvcuda;

#define D_MODEL 1024
#define D_STATE 64
#define D_CONV  4
#define D_INNER 2048
#define NHEADS  32
#define HEADDIM 64
#define D_PROJ  8224   // 2*D_INNER + NHEADS*(2*D_STATE+1)
#define BATCH   2
#define SEQLEN  1024
#define NTOK    (BATCH*SEQLEN)   // 2048
#define CHUNK   64
#define NCHUNK  (SEQLEN/CHUNK)   // 16

// Scratch (allocation-free rule: __device__ globals)
__device__ float g_proj [(size_t)NTOK * D_PROJ];          // 67 MB
__device__ float g_xconv[(size_t)NTOK * D_INNER];         // 17 MB
__device__ float g_y    [(size_t)NTOK * D_INNER];         // 17 MB
__device__ float g_S    [(size_t)BATCH*NHEADS*SEQLEN];    // 256 KB
__device__ float g_hloc [(size_t)BATCH*NHEADS*NCHUNK*D_STATE*HEADDIM]; // 17 MB
__device__ float g_hin  [(size_t)BATCH*NHEADS*NCHUNK*D_STATE*HEADDIM]; // 17 MB

// Pre-split bf16 operands (hi/lo) for the tensor-core GEMMs
__device__ __nv_bfloat16 g_Win_h [(size_t)D_PROJ * D_MODEL];
__device__ __nv_bfloat16 g_Win_l [(size_t)D_PROJ * D_MODEL];
__device__ __nv_bfloat16 g_xh    [(size_t)NTOK * D_MODEL];
__device__ __nv_bfloat16 g_xl    [(size_t)NTOK * D_MODEL];
__device__ __nv_bfloat16 g_Wout_h[(size_t)D_MODEL * D_INNER];
__device__ __nv_bfloat16 g_Wout_l[(size_t)D_MODEL * D_INNER];
__device__ __nv_bfloat16 g_yh    [(size_t)NTOK * D_INNER];
__device__ __nv_bfloat16 g_yl    [(size_t)NTOK * D_INNER];

// ---------------------------------------------------------------------------
// Split f32 -> (hi, lo) bf16. n must be divisible by 4.
// ---------------------------------------------------------------------------
__global__ __launch_bounds__(256) void split_kernel(
    const float* __restrict__ src, __nv_bfloat16* __restrict__ hi,
    __nv_bfloat16* __restrict__ lo, int n4)
{
    const int i = blockIdx.x * 256 + threadIdx.x;
    if (i >= n4) return;
    const float4 v = reinterpret_cast<const float4*>(src)[i];
    __nv_bfloat162 h01 = __floats2bfloat162_rn(v.x, v.y);
    __nv_bfloat162 h23 = __floats2bfloat162_rn(v.z, v.w);
    __nv_bfloat162 l01 = __floats2bfloat162_rn(v.x - __bfloat162float(h01.x),
                                               v.y - __bfloat162float(h01.y));
    __nv_bfloat162 l23 = __floats2bfloat162_rn(v.z - __bfloat162float(h23.x),
                                               v.w - __bfloat162float(h23.y));
    uint2 hv, lv;
    hv.x = *reinterpret_cast<uint32_t*>(&h01);
    hv.y = *reinterpret_cast<uint32_t*>(&h23);
    lv.x = *reinterpret_cast<uint32_t*>(&l01);
    lv.y = *reinterpret_cast<uint32_t*>(&l23);
    reinterpret_cast<uint2*>(hi)[i] = hv;
    reinterpret_cast<uint2*>(lo)[i] = lv;
}

// ===========================================================================
// Double-buffered cp.async bf16-split wmma GEMM "NT".
// C[m,n] = sum_k A[m,k]*B[n,k] with A=Ah+Al, B=Bh+Bl (bf16 pairs);
// C ≈ Ah*Bh + Ah*Bl + Al*Bh (f32 accum).
// CTA tile 128x128, K-chunk 32, 256 threads = 8 warps (2m x 4n),
// warp tile 64x32 = 4x2 wmma 16x16x16 fragments.
// smem: 2 buffers x 4 tiles x 128 rows x GLD(=40) bf16 = 81920 B dynamic.
// GLD=40 (80 B row stride) -> ldmatrix conflict-free.
// Requires M%128==0, K%32==0, N%16==0.
// ===========================================================================
#define GLD 40
#define TILE_E (128 * GLD)              // bf16 elems per tile
#define GEMM_SMEM (2 * 4 * TILE_E * 2)  // bytes = 81920

__device__ __forceinline__ void cp16(uint32_t dst, const void* src, bool valid) {
    const int sz = valid ? 16 : 0;
    asm volatile("cp.async.cg.shared.global [%0], [%1], 16, %2;\n"
                 :: "r"(dst), "l"(src), "r"(sz));
}
__device__ __forceinline__ void cp_commit() {
    asm volatile("cp.async.commit_group;\n" ::: "memory");
}
__device__ __forceinline__ void cp_wait1() {
    asm volatile("cp.async.wait_group 1;\n" ::: "memory");
}

__global__ __launch_bounds__(256) void gemm_wmma_db(
    const __nv_bfloat16* __restrict__ Ah, const __nv_bfloat16* __restrict__ Al,
    const __nv_bfloat16* __restrict__ Bh, const __nv_bfloat16* __restrict__ Bl,
    float* __restrict__ C, int M, int N, int K)
{
    extern __shared__ __nv_bfloat16 sm[];
    const int tid = threadIdx.x;
    const int wid = tid >> 5;
    const int wm  = wid >> 2;        // 0..1
    const int wn  = wid & 3;         // 0..3
    const int bm  = blockIdx.y * 128;
    const int bn  = blockIdx.x * 128;

    const uint32_t sm_base = (uint32_t)__cvta_generic_to_shared(sm);

    // per-thread cp.async assignment: 2048 16B-chunks per buffer, 8 per thread
    // chunk id: tile t = id>>9, row = (id>>2)&127, c4 = id&3
    const __nv_bfloat16* srcs[4] = {Ah, Al, Bh, Bl};

    auto load_buf = [&](int k0, int buf) {
        #pragma unroll
        for (int it = 0; it < 8; it++) {
            const int id  = it * 256 + tid;
            const int t   = id >> 9;
            const int row = (id >> 2) & 127;
            const int c4  = id & 3;
            const bool isB = (t >= 2);
            const int grow = (isB ? bn : bm) + row;
            const bool valid = isB ? (grow < N) : true;
            const __nv_bfloat16* src =
                srcs[t] + (size_t)(valid ? grow : 0) * K + k0 + c4 * 8;
            const uint32_t dst = sm_base +
                ((buf * 4 + t) * TILE_E + row * GLD + c4 * 8) * 2;
            cp16(dst, src, valid);
        }
        cp_commit();
    };

    wmma::fragment<wmma::accumulator, 16, 16, 16, float> acc[4][2];
    #pragma unroll
    for (int i = 0; i < 4; i++)
        #pragma unroll
        for (int j = 0; j < 2; j++)
            wmma::fill_fragment(acc[i][j], 0.f);

    const int nch = K >> 5;
    load_buf(0, 0);

    for (int ch = 0; ch < nch; ch++) {
        if (ch + 1 < nch) load_buf((ch + 1) << 5, (ch + 1) & 1);
        else cp_commit();                 // keep group accounting uniform
        cp_wait1();
        __syncthreads();

        const __nv_bfloat16* sAh = sm + ((ch & 1) * 4 + 0) * TILE_E;
        const __nv_bfloat16* sAl = sm + ((ch & 1) * 4 + 1) * TILE_E;
        const __nv_bfloat16* sBh = sm + ((ch & 1) * 4 + 2) * TILE_E;
        const __nv_bfloat16* sBl = sm + ((ch & 1) * 4 + 3) * TILE_E;

        #pragma unroll
        for (int ks = 0; ks < 32; ks += 16) {
            wmma::fragment<wmma::matrix_a, 16, 16, 16, __nv_bfloat16,
                           wmma::row_major> ah[4], al[4];
            wmma::fragment<wmma::matrix_b, 16, 16, 16, __nv_bfloat16,
                           wmma::col_major> bh[2], bl[2];
            #pragma unroll
            for (int i = 0; i < 4; i++) {
                const int r = (wm * 64 + i * 16) * GLD + ks;
                wmma::load_matrix_sync(ah[i], &sAh[r], GLD);
                wmma::load_matrix_sync(al[i], &sAl[r], GLD);
            }
            #pragma unroll
            for (int j = 0; j < 2; j++) {
                const int r = (wn * 32 + j * 16) * GLD + ks;
                wmma::load_matrix_sync(bh[j], &sBh[r], GLD);
                wmma::load_matrix_sync(bl[j], &sBl[r], GLD);
            }
            #pragma unroll
            for (int i = 0; i < 4; i++)
                #pragma unroll
                for (int j = 0; j < 2; j++) {
                    wmma::mma_sync(acc[i][j], ah[i], bh[j], acc[i][j]);
                    wmma::mma_sync(acc[i][j], ah[i], bl[j], acc[i][j]);
                    wmma::mma_sync(acc[i][j], al[i], bh[j], acc[i][j]);
                }
        }
        __syncthreads();
    }

    #pragma unroll
    for (int i = 0; i < 4; i++) {
        const int m0 = bm + wm * 64 + i * 16;
        #pragma unroll
        for (int j = 0; j < 2; j++) {
            const int n0 = bn + wn * 32 + j * 16;
            if (n0 < N)
                wmma::store_matrix_sync(C + (size_t)m0 * N + n0, acc[i][j],
                                        N, wmma::mem_row_major);
        }
    }
}

// ---------------------------------------------------------------------------
// Depthwise causal conv (width 4) + bias + SiLU
// ---------------------------------------------------------------------------
__global__ __launch_bounds__(256) void conv_silu_kernel(
    const float* __restrict__ conv_w, const float* __restrict__ conv_b)
{
    const int idx = blockIdx.x * blockDim.x + threadIdx.x;
    if (idx >= NTOK * D_INNER) return;
    const int c   = idx & (D_INNER - 1);
    const int tok = idx / D_INNER;
    const int b   = tok / SEQLEN;
    const int l   = tok - b * SEQLEN;

    float acc = conv_b[c];
    #pragma unroll
    for (int j = 0; j < D_CONV; j++) {
        const int ll = l - (D_CONV - 1) + j;
        if (ll >= 0)
            acc = fmaf(conv_w[c * D_CONV + j],
                       g_proj[(size_t)(b * SEQLEN + ll) * D_PROJ + c], acc);
    }
    const float sv = acc / (1.f + __expf(-acc));   // SiLU
    g_xconv[(size_t)tok * D_INNER + c] = sv;
}

__device__ __forceinline__ float softplus_f(float r) {
    return (r > 20.f) ? r : log1pf(__expf(r));
}

// ---------------------------------------------------------------------------
// Phase A (v4): precompute-then-scan. One CTA per (head, batch, chunk).
// ---------------------------------------------------------------------------
__global__ __launch_bounds__(64) void scan_chunk_kernel(
    const float* __restrict__ A_log, const float* __restrict__ dt_bias)
{
    const int h   = blockIdx.x;
    const int b   = blockIdx.y;
    const int c   = blockIdx.z;
    const int tid = threadIdx.x;

    __shared__ float4 sDAB[CHUNK][D_STATE / 2];
    __shared__ float4 sCp [CHUNK][D_STATE / 4];

    const float Anegs = -__expf(A_log[h * D_STATE + tid]);
    const float dtb   = dt_bias[h];

    const int bc_off = 2 * D_INNER + h * (2 * D_STATE + 1);
    const int tok0   = b * SEQLEN + c * CHUNK;

    if (tid < 32) {
        const float d0 = softplus_f(
            g_proj[(size_t)(tok0 + tid) * D_PROJ + bc_off + 2 * D_STATE] + dtb);
        const float d1 = softplus_f(
            g_proj[(size_t)(tok0 + 32 + tid) * D_PROJ + bc_off + 2 * D_STATE] + dtb);
        float v = d0;
        #pragma unroll
        for (int off = 1; off < 32; off <<= 1) {
            const float n = __shfl_up_sync(0xffffffffu, v, off);
            if (tid >= off) v += n;
        }
        const float tot0 = __shfl_sync(0xffffffffu, v, 31);
        float w2 = d1;
        #pragma unroll
        for (int off = 1; off < 32; off <<= 1) {
            const float n = __shfl_up_sync(0xffffffffu, w2, off);
            if (tid >= off) w2 += n;
        }
        float* Sout = g_S + (size_t)(b * NHEADS + h) * SEQLEN + c * CHUNK;
        Sout[tid]      = v;
        Sout[32 + tid] = tot0 + w2;
    }

    {
        float2* dabRow = reinterpret_cast<float2*>(&sDAB[0][0]);
        float*  cRow   = reinterpret_cast<float*>(&sCp[0][0]);
        #pragma unroll 4
        for (int t = 0; t < CHUNK; t++) {
            const float* pr = g_proj + (size_t)(tok0 + t) * D_PROJ + bc_off;
            const float dtv = softplus_f(pr[2 * D_STATE] + dtb);
            const float Bv  = pr[tid];
            const float Cv  = pr[D_STATE + tid];
            dabRow[t * D_STATE + tid] = make_float2(__expf(Anegs * dtv), Bv * dtv);
            cRow  [t * D_STATE + tid] = Cv;
        }
    }
    __syncthreads();

    float hreg[D_STATE];
    #pragma unroll
    for (int s = 0; s < D_STATE; s++) hreg[s] = 0.f;

    const int x_off = h * HEADDIM + tid;
    float px = g_xconv[(size_t)tok0 * D_INNER + x_off];

    for (int t = 0; t < CHUNK; t++) {
        const float xd = px;
        const int tn = (t + 1 < CHUNK) ? (t + 1) : t;
        px = g_xconv[(size_t)(tok0 + tn) * D_INNER + x_off];

        float y0 = 0.f, y1 = 0.f, y2 = 0.f, y3 = 0.f;
        #pragma unroll
        for (int j = 0; j < D_STATE / 4; j++) {
            const float4 ab0 = sDAB[t][2 * j + 0];
            const float4 ab1 = sDAB[t][2 * j + 1];
            const float4 cc  = sCp[t][j];
            hreg[4*j + 0] = fmaf(ab0.x, hreg[4*j + 0], ab0.y * xd);
            hreg[4*j + 1] = fmaf(ab0.z, hreg[4*j + 1], ab0.w * xd);
            hreg[4*j + 2] = fmaf(ab1.x, hreg[4*j + 2], ab1.y * xd);
            hreg[4*j + 3] = fmaf(ab1.z, hreg[4*j + 3], ab1.w * xd);
            y0 = fmaf(cc.x, hreg[4*j + 0], y0);
            y1 = fmaf(cc.y, hreg[4*j + 1], y1);
            y2 = fmaf(cc.z, hreg[4*j + 2], y2);
            y3 = fmaf(cc.w, hreg[4*j + 3], y3);
        }
        g_y[(size_t)(tok0 + t) * D_INNER + x_off] = (y0 + y1) + (y2 + y3);
    }

    float* hl = g_hloc + ((size_t)(b * NHEADS + h) * NCHUNK + c) * (D_STATE * HEADDIM);
    #pragma unroll
    for (int s = 0; s < D_STATE; s++)
        hl[s * HEADDIM + tid] = hreg[s];
}

// ---------------------------------------------------------------------------
// Phase B: cross-chunk state recurrence. One thread per (b,h,s,d).
// ---------------------------------------------------------------------------
__global__ __launch_bounds__(256) void chunk_state_kernel(
    const float* __restrict__ A_log)
{
    const int gid = blockIdx.x * 256 + threadIdx.x;
    const int dd = gid & 63;
    const int s  = (gid >> 6) & 63;
    const int hh = (gid >> 12) & 31;
    const int bb = gid >> 17;

    const float Aneg = -__expf(A_log[hh * D_STATE + s]);
    const size_t base = ((size_t)(bb * NHEADS + hh) * NCHUNK) * (D_STATE * HEADDIM)
                      + (size_t)s * HEADDIM + dd;
    const float* Srow = g_S + (size_t)(bb * NHEADS + hh) * SEQLEN;

    float hv = 0.f;
    #pragma unroll
    for (int cc = 0; cc < NCHUNK; cc++) {
        g_hin[base + (size_t)cc * (D_STATE * HEADDIM)] = hv;
        const float ST = Srow[cc * CHUNK + CHUNK - 1];
        hv = fmaf(__expf(Aneg * ST), hv,
                  g_hloc[base + (size_t)cc * (D_STATE * HEADDIM)]);
    }
}

// ---------------------------------------------------------------------------
// Phase C: y_t += sum_s C_t[s]*exp(Aneg_s*S_t)*h_in[s,d], then
// finalize g_y = (y + D*x) * silu(z). One CTA per (head,batch,chunk).
// ---------------------------------------------------------------------------
__global__ __launch_bounds__(256) void ycorrect_kernel(
    const float* __restrict__ A_log, const float* __restrict__ Dp)
{
    const int h   = blockIdx.x;
    const int b   = blockIdx.y;
    const int c   = blockIdx.z;
    const int tid = threadIdx.x;

    __shared__ float sHin[D_STATE * HEADDIM];   // [s][d]
    __shared__ float sCt[CHUNK * 65];           // [t][s], padded
    __shared__ float sS[CHUNK];
    __shared__ float sAneg[D_STATE];

    const size_t hin_base = ((size_t)(b * NHEADS + h) * NCHUNK + c) * (D_STATE * HEADDIM);
    for (int i = tid; i < D_STATE * HEADDIM; i += 256)
        sHin[i] = g_hin[hin_base + i];

    if (tid < D_STATE) {
        sAneg[tid] = -__expf(A_log[h * D_STATE + tid]);
        sS[tid] = g_S[(size_t)(b * NHEADS + h) * SEQLEN + c * CHUNK + tid];
    }
    __syncthreads();

    const int bc_off = 2 * D_INNER + h * (2 * D_STATE + 1);
    const int tok0   = b * SEQLEN + c * CHUNK;

    #pragma unroll
    for (int j = 0; j < 16; j++) {
        const int idx = j * 256 + tid;
        const int t = idx >> 6, s = idx & 63;
        const float Cv = g_proj[(size_t)(tok0 + t) * D_PROJ + bc_off + D_STATE + s];
        sCt[t * 65 + s] = Cv * __expf(sAneg[s] * sS[t]);
    }
    __syncthreads();

    const int t  = tid & 63;
    const int d0 = (tid >> 6) * 16;

    float acc[16];
    #pragma unroll
    for (int i = 0; i < 16; i++) acc[i] = 0.f;

    #pragma unroll 8
    for (int s = 0; s < D_STATE; s++) {
        const float ct = sCt[t * 65 + s];
        const float* hr = &sHin[s * HEADDIM + d0];
        #pragma unroll
        for (int i = 0; i < 16; i += 4) {
            const float4 hv = *reinterpret_cast<const float4*>(hr + i);
            acc[i + 0] = fmaf(ct, hv.x, acc[i + 0]);
            acc[i + 1] = fmaf(ct, hv.y, acc[i + 1]);
            acc[i + 2] = fmaf(ct, hv.z, acc[i + 2]);
            acc[i + 3] = fmaf(ct, hv.w, acc[i + 3]);
        }
    }

    const float Dh  = Dp[h];
    const int tok   = tok0 + t;
    const float* prow = g_proj  + (size_t)tok * D_PROJ;
    const float* xrow = g_xconv + (size_t)tok * D_INNER + h * HEADDIM;
    float*       yrow = g_y     + (size_t)tok * D_INNER + h * HEADDIM;
    #pragma unroll
    for (int i = 0; i < 16; i++) {
        const int dd = d0 + i;
        const float xv = xrow[dd];
        const float zv = prow[D_INNER + h * HEADDIM + dd];
        const float y  = yrow[dd] + acc[i] + Dh * xv;
        const float sz = zv / (1.f + __expf(-zv));
        yrow[dd] = y * sz;
    }
}

// ---------------------------------------------------------------------------
extern "C" void kernel_launch(void* const* d_in, const int* in_sizes, int n_in,
                              void* d_out, int out_size)
{
    const float* x       = (const float*)d_in[0];
    const float* W_in    = (const float*)d_in[1];
    const float* conv_w  = (const float*)d_in[2];
    const float* conv_b  = (const float*)d_in[3];
    const float* A_log   = (const float*)d_in[4];
    const float* Dp      = (const float*)d_in[5];
    const float* dt_bias = (const float*)d_in[6];
    const float* W_out   = (const float*)d_in[7];
    float* out = (float*)d_out;

    (void)in_sizes; (void)n_in; (void)out_size;

    float* proj = nullptr;  cudaGetSymbolAddress((void**)&proj, g_proj);
    float* yptr = nullptr;  cudaGetSymbolAddress((void**)&yptr, g_y);
    __nv_bfloat16 *winh, *winl, *xh, *xl, *woh, *wol, *yh, *yl;
    cudaGetSymbolAddress((void**)&winh, g_Win_h);
    cudaGetSymbolAddress((void**)&winl, g_Win_l);
    cudaGetSymbolAddress((void**)&xh,   g_xh);
    cudaGetSymbolAddress((void**)&xl,   g_xl);
    cudaGetSymbolAddress((void**)&woh,  g_Wout_h);
    cudaGetSymbolAddress((void**)&wol,  g_Wout_l);
    cudaGetSymbolAddress((void**)&yh,   g_yh);
    cudaGetSymbolAddress((void**)&yl,   g_yl);

    cudaFuncSetAttribute(gemm_wmma_db,
                         cudaFuncAttributeMaxDynamicSharedMemorySize, GEMM_SMEM);

    // 0) pre-split inputs to bf16 hi/lo   (launches 1-3; capture = launch 4)
    {
        const int nW = D_PROJ * D_MODEL / 4;
        split_kernel<<<(nW + 255) / 256, 256>>>(W_in, winh, winl, nW);
        const int nx = NTOK * D_MODEL / 4;
        split_kernel<<<(nx + 255) / 256, 256>>>(x, xh, xl, nx);
        const int nWo = D_MODEL * D_INNER / 4;
        split_kernel<<<(nWo + 255) / 256, 256>>>(W_out, woh, wol, nWo);
    }

    // 1) proj = x @ W_in^T   (M=2048, N=8224, K=1024)  <-- ncu capture
    {
        dim3 grid((D_PROJ + 127) / 128, NTOK / 128);   // 65 x 16
        gemm_wmma_db<<<grid, 256, GEMM_SMEM>>>(xh, xl, winh, winl, proj,
                                               NTOK, D_PROJ, D_MODEL);
    }

    // 2) depthwise conv + SiLU
    {
        const int total = NTOK * D_INNER;
        conv_silu_kernel<<<(total + 255) / 256, 256>>>(conv_w, conv_b);
    }

    // 3a) chunk-local scans
    {
        dim3 grid(NHEADS, BATCH, NCHUNK);
        scan_chunk_kernel<<<grid, 64>>>(A_log, dt_bias);
    }

    // 3b) cross-chunk state recurrence
    {
        const int total = BATCH * NHEADS * D_STATE * HEADDIM;   // 262144
        chunk_state_kernel<<<total / 256, 256>>>(A_log);
    }

    // 3c) y correction + D*x + gating
    {
        dim3 grid(NHEADS, BATCH, NCHUNK);
        ycorrect_kernel<<<grid, 256>>>(A_log, Dp);
    }

    // 3d) split finalized y
    {
        const int ny = NTOK * D_INNER / 4;
        split_kernel<<<(ny + 255) / 256, 256>>>(yptr, yh, yl, ny);
    }

    // 4) out = y @ W_out^T   (M=2048, N=1024, K=2048)
    {
        dim3 grid(D_MODEL / 128, NTOK / 128);          // 8 x 16
        gemm_wmma_db<<<grid, 256, GEMM_SMEM>>>(yh, yl, woh, wol, out,
                                               NTOK, D_MODEL, D_INNER);
    }
}